// round 9
// baseline (speedup 1.0000x reference)
#include <cuda_runtime.h>
#include <cuda_fp16.h>
#include <math.h>
#include <stdint.h>

// Problem constants
#define Vv   50257
#define Tt   2048
#define Ee   768
#define Hh   12
#define DhD  64
#define Bb   2
#define BT   (Bb*Tt)      // 4096
#define BH   (Bb*Hh)      // 24
#define QKVN (3*Ee)       // 2304
#define NPAD 50432        // V padded to multiple of 256
#define NBY  (NPAD/256)   // 197 logits column tiles

// ---------------- scratch (static device globals; no runtime allocs) ----------------
__device__ __half g_att[(size_t)BH*Tt*Tt];         // 201 MB raw scores (fp16)
__device__ float  g_rowlogp[BT];
__device__ float  g_partZ[(size_t)BT*NBY];         // per-row partial sumexp
__device__ float2 g_stat[(size_t)BH*Tt];           // (m_s, 1/Z_s) per column
__device__ __half g_a2q[(size_t)BT*2304];          // h split [hi|hi|lo]
__device__ __half g_b2q[(size_t)QKVN*2304];        // Wp^T split [hi|lo|hi]
__device__ __half g_qkh[(size_t)BT*1536];          // q|k fp16
__device__ float  g_v[(size_t)BT*Ee];              // v fp32
__device__ __half g_vt[(size_t)BH*DhD*Tt];         // v^T fp16 per head
__device__ __half g_a2L[(size_t)BT*768];           // o hi
__device__ __half g_b2L[(size_t)NPAD*768];         // Wout^T hi

// ================= PTX helpers (baseline ISA only) =================
__device__ __forceinline__ uint32_t smem_u32(const void* p) {
    uint32_t a;
    asm("{ .reg .u64 t; cvta.to.shared.u64 t, %1; cvt.u32.u64 %0, t; }" : "=r"(a) : "l"(p));
    return a;
}
#define SWZ(o) ((o) ^ (((o) >> 3) & 0x70))

__device__ __forceinline__ void cp16(uint32_t dst, const void* src) {
    asm volatile("cp.async.cg.shared.global [%0], [%1], 16;" :: "r"(dst), "l"(src));
}
#define CP_COMMIT() asm volatile("cp.async.commit_group;" ::: "memory")
#define CP_WAIT1()  asm volatile("cp.async.wait_group 1;" ::: "memory")
#define CP_WAIT0()  asm volatile("cp.async.wait_group 0;" ::: "memory")

__device__ __forceinline__ void ldm_x4(uint32_t* r, uint32_t addr) {
    asm volatile("ldmatrix.sync.aligned.m8n8.x4.shared.b16 {%0,%1,%2,%3}, [%4];"
                 : "=r"(r[0]), "=r"(r[1]), "=r"(r[2]), "=r"(r[3]) : "r"(addr));
}
__device__ __forceinline__ void mma16816(float* d, const uint32_t* a, const uint32_t* b) {
    asm volatile(
        "mma.sync.aligned.m16n8k16.row.col.f32.f16.f16.f32 "
        "{%0,%1,%2,%3},{%4,%5,%6,%7},{%8,%9},{%0,%1,%2,%3};"
        : "+f"(d[0]), "+f"(d[1]), "+f"(d[2]), "+f"(d[3])
        : "r"(a[0]), "r"(a[1]), "r"(a[2]), "r"(a[3]), "r"(b[0]), "r"(b[1]));
}

// Taylor exp: ~1e-5 for |x|<=0.25; fallback __expf otherwise (handles -inf -> 0)
__device__ __forceinline__ float expw(float x) {
    if (x >= -0.25f) {
        float p = 0.041666668f;
        p = fmaf(p, x, 0.16666667f);
        p = fmaf(p, x, 0.5f);
        p = fmaf(p, x, 1.0f);
        p = fmaf(p, x, 1.0f);
        return p;
    }
    return __expf(x);
}
__device__ __forceinline__ float expw0(float x) {
    if (fabsf(x) <= 0.25f) {
        float p = 0.041666668f;
        p = fmaf(p, x, 0.16666667f);
        p = fmaf(p, x, 0.5f);
        p = fmaf(p, x, 1.0f);
        p = fmaf(p, x, 1.0f);
        return p;
    }
    return __expf(x);
}

// ---------------- 1) embed + split h to fp16 [hi|hi|lo] ----------------
__global__ void embed_split_kernel(const int* __restrict__ x,
                                   const float* __restrict__ tok,
                                   const float* __restrict__ pos)
{
    int idx = blockIdx.x * blockDim.x + threadIdx.x;
    if (idx >= BT * Ee) return;
    int e  = idx % Ee;
    int bt = idx / Ee;
    int t  = bt % Tt;
    float h = tok[(size_t)x[bt]*Ee + e] + pos[(size_t)t*Ee + e];
    __half hi = __float2half_rn(h);
    __half lo = __float2half_rn(h - __half2float(hi));
    size_t rb = (size_t)bt * 2304;
    g_a2q[rb + e]        = hi;
    g_a2q[rb + 768 + e]  = hi;
    g_a2q[rb + 1536 + e] = lo;
}

// ---------------- 2a) pack Wq/Wk/Wv -> B2q ----------------
__global__ void packB2q_kernel(const float* __restrict__ Wq,
                               const float* __restrict__ Wk,
                               const float* __restrict__ Wv)
{
    int idx = blockIdx.x * blockDim.x + threadIdx.x;
    if (idx >= QKVN * Ee) return;
    int e = idx % Ee;
    int n = idx / Ee;
    int w = n / Ee;
    int r = n % Ee;
    int h = r / DhD;
    int d = r % DhD;
    const float* W = (w == 0) ? Wq : (w == 1) ? Wk : Wv;
    float v = W[(size_t)h*Ee*DhD + (size_t)e*DhD + d];
    __half hi = __float2half_rn(v);
    __half lo = __float2half_rn(v - __half2float(hi));
    size_t rb = (size_t)n * 2304;
    g_b2q[rb + e]        = hi;
    g_b2q[rb + 768 + e]  = lo;
    g_b2q[rb + 1536 + e] = hi;
}

// ---------------- 2b) transpose Wout -> B2L ----------------
__global__ __launch_bounds__(256)
void convB_kernel(const float* __restrict__ W)
{
    __shared__ float tile[32][33];
    const int n0 = blockIdx.x * 32;
    const int k0 = blockIdx.y * 32;
    const int tx = threadIdx.x;
    const int ty = threadIdx.y;
#pragma unroll
    for (int i = 0; i < 32; i += 8) {
        int k = k0 + ty + i, n = n0 + tx;
        tile[ty + i][tx] = (n < Vv) ? W[(size_t)k * Vv + n] : 0.f;
    }
    __syncthreads();
#pragma unroll
    for (int i = 0; i < 32; i += 8) {
        int n = n0 + ty + i, k = k0 + tx;
        g_b2L[(size_t)n * 768 + k] = __float2half_rn(tile[tx][ty + i]);
    }
}

// ---------------- 3) persistent mma GEMM: CTA 128(M) x 256(N), multi N-tile ----------------
// Each CTA sweeps N tiles ti = blockIdx.y + j*gridDim.y; the 3-stage cp.async pipeline
// runs continuously across tile boundaries (no per-tile prologue bubble).
#define STAGE_BYTES 49152      // 16KB A + 32KB B

__device__ __forceinline__ void load_chunk2(uint32_t sbase, int buf,
                                            const __half* __restrict__ A2, int kcol, int ka,
                                            const __half* __restrict__ B2, int kb,
                                            int bm, int bn, int tid)
{
    uint32_t dstA = sbase + buf * STAGE_BYTES;
    uint32_t dstB = dstA + 16384;
#pragma unroll
    for (int it = 0; it < 4; it++) {
        int task = tid + it * 256;
        int row  = task >> 3;
        int seg  = task & 7;
        cp16(dstA + SWZ(row * 128 + seg * 16),
             A2 + (size_t)(bm + row) * ka + kcol + seg * 8);
    }
#pragma unroll
    for (int it = 0; it < 8; it++) {
        int task = tid + it * 256;
        int row  = task >> 3;            // 0..255
        int seg  = task & 7;
        cp16(dstB + SWZ(row * 128 + seg * 16),
             B2 + (size_t)(bn + row) * kb + kcol + seg * 8);
    }
}

__global__ __launch_bounds__(256, 1)
void mma_gemm_kernel(const __half* __restrict__ A2, const __half* __restrict__ B2,
                     int nchunk, int ka, int kb, int ntiles, int Ncols,
                     const float* __restrict__ bias, float* __restrict__ out, size_t ldc,
                     int mode, __half* __restrict__ half_out, float* __restrict__ vout,
                     float* __restrict__ partZ)
{
    extern __shared__ char smem[];
    __shared__ float sred[512];
    const uint32_t sbase = smem_u32(smem);
    const int tid  = threadIdx.x;
    const int wid  = tid >> 5;
    const int lane = tid & 31;
    const int bm = blockIdx.x * 128;
    const int wm = wid >> 2;      // 0..1
    const int wn = wid & 3;       // 0..3 (64-col slabs)

    int cnt = 0;
    for (int ti = blockIdx.y; ti < ntiles; ti += (int)gridDim.y) cnt++;
    if (cnt == 0) return;
    const int total = cnt * nchunk;

    float acc[4][8][4];
#pragma unroll
    for (int i = 0; i < 4; i++)
#pragma unroll
        for (int j = 0; j < 8; j++)
#pragma unroll
            for (int q = 0; q < 4; q++) acc[i][j][q] = 0.f;

    // prologue: global chunks 0, 1 (both in tile j=0 since nchunk >= 12)
    {
        int bn0 = blockIdx.y * 256;
        load_chunk2(sbase, 0, A2, 0, ka, B2, kb, bm, bn0, tid); CP_COMMIT();
        if (total > 1) load_chunk2(sbase, 1, A2, 64, ka, B2, kb, bm, bn0, tid);
        CP_COMMIT();
    }

    int jt = 0;   // current owned-tile ordinal
    for (int g = 0; g < total; g++) {
        const int c = g - jt * nchunk;
        CP_WAIT1();
        __syncthreads();

        int gn = g + 2;
        if (gn < total) {
            int jn = gn / nchunk;
            int cn = gn - jn * nchunk;
            int bnn = (blockIdx.y + jn * (int)gridDim.y) * 256;
            load_chunk2(sbase, gn % 3, A2, cn * 64, ka, B2, kb, bm, bnn, tid);
        }
        CP_COMMIT();

        const uint32_t sa = sbase + (g % 3) * STAGE_BYTES;
        const uint32_t sb = sa + 16384;

#pragma unroll
        for (int kk = 0; kk < 4; kk++) {
            uint32_t afr[4][4];
#pragma unroll
            for (int i = 0; i < 4; i++) {
                int row = wm * 64 + i * 16 + (lane & 15);
                uint32_t off = row * 128 + kk * 32 + (lane >> 4) * 16;
                ldm_x4(afr[i], sa + SWZ(off));
            }
#pragma unroll
            for (int p = 0; p < 4; p++) {
                int rown = wn * 64 + p * 16 + ((lane >> 4) & 1) * 8 + (lane & 7);
                uint32_t off = rown * 128 + kk * 32 + ((lane >> 3) & 1) * 16;
                uint32_t r[4];
                ldm_x4(r, sb + SWZ(off));
                uint32_t b0[2] = { r[0], r[1] };
                uint32_t b1[2] = { r[2], r[3] };
#pragma unroll
                for (int i = 0; i < 4; i++) {
                    mma16816(acc[i][2*p],     afr[i], b0);
                    mma16816(acc[i][2*p + 1], afr[i], b1);
                }
            }
        }

        if (c == nchunk - 1) {
            // ---- tile epilogue (pipeline for next tile already in flight) ----
            const int tile_idx = blockIdx.y + jt * (int)gridDim.y;
            const int bn = tile_idx * 256;
            if (mode == 0) {
                float rs[4][2];
#pragma unroll
                for (int i = 0; i < 4; i++) { rs[i][0] = 0.f; rs[i][1] = 0.f; }
#pragma unroll
                for (int i = 0; i < 4; i++) {
                    int m0 = bm + wm * 64 + i * 16 + (lane >> 2);
                    float* row0 = out + (size_t)m0 * ldc;
                    float* row1 = out + (size_t)(m0 + 8) * ldc;
#pragma unroll
                    for (int j = 0; j < 8; j++) {
                        int n = bn + wn * 64 + j * 8 + (lane & 3) * 2;
                        if (n < Ncols) {
                            float v0 = acc[i][j][0] + bias[n];
                            float v2 = acc[i][j][2] + bias[n];
                            row0[n] = v0; row1[n] = v2;
                            rs[i][0] += expw0(v0); rs[i][1] += expw0(v2);
                        }
                        if (n + 1 < Ncols) {
                            float v1 = acc[i][j][1] + bias[n + 1];
                            float v3 = acc[i][j][3] + bias[n + 1];
                            row0[n + 1] = v1; row1[n + 1] = v3;
                            rs[i][0] += expw0(v1); rs[i][1] += expw0(v3);
                        }
                    }
                }
                if (partZ) {
#pragma unroll
                    for (int i = 0; i < 4; i++) {
                        rs[i][0] += __shfl_xor_sync(0xffffffff, rs[i][0], 1);
                        rs[i][0] += __shfl_xor_sync(0xffffffff, rs[i][0], 2);
                        rs[i][1] += __shfl_xor_sync(0xffffffff, rs[i][1], 1);
                        rs[i][1] += __shfl_xor_sync(0xffffffff, rs[i][1], 2);
                    }
                    __syncthreads();
                    if ((lane & 3) == 0) {
                        int r4 = lane >> 2;
#pragma unroll
                        for (int i = 0; i < 4; i++) {
                            sred[(wm * 64 + i * 16 + r4) * 4 + wn]     = rs[i][0];
                            sred[(wm * 64 + i * 16 + 8 + r4) * 4 + wn] = rs[i][1];
                        }
                    }
                    __syncthreads();
                    if (tid < 128) {
                        float z = sred[tid * 4] + sred[tid * 4 + 1]
                                + sred[tid * 4 + 2] + sred[tid * 4 + 3];
                        partZ[(size_t)(bm + tid) * NBY + tile_idx] = z;
                    }
                }
            } else {
#pragma unroll
                for (int i = 0; i < 4; i++) {
                    int m0 = bm + wm * 64 + i * 16 + (lane >> 2);
#pragma unroll
                    for (int j = 0; j < 8; j++) {
                        int n = bn + wn * 64 + j * 8 + (lane & 3) * 2;
                        if (n < 1536) {
                            __half* r0 = half_out + (size_t)m0 * 1536;
                            __half* r1 = half_out + (size_t)(m0 + 8) * 1536;
                            r0[n]     = __float2half_rn(acc[i][j][0]);
                            r0[n + 1] = __float2half_rn(acc[i][j][1]);
                            r1[n]     = __float2half_rn(acc[i][j][2]);
                            r1[n + 1] = __float2half_rn(acc[i][j][3]);
                        } else {
                            int nv = n - 1536;
                            float* r0 = vout + (size_t)m0 * 768;
                            float* r1 = vout + (size_t)(m0 + 8) * 768;
                            r0[nv]     = acc[i][j][0];
                            r0[nv + 1] = acc[i][j][1];
                            r1[nv]     = acc[i][j][2];
                            r1[nv + 1] = acc[i][j][3];
                        }
                    }
                }
            }
            // reset accumulators for next tile
#pragma unroll
            for (int i = 0; i < 4; i++)
#pragma unroll
                for (int j = 0; j < 8; j++)
#pragma unroll
                    for (int q = 0; q < 4; q++) acc[i][j][q] = 0.f;
            jt++;
        }
    }
}

// ---------------- 3c) v^T transpose: g_v fp32 -> g_vt fp16 [bh][d][t] ----------------
__global__ __launch_bounds__(256)
void vt_kernel()
{
    __shared__ float tile[32][33];
    const int t0 = blockIdx.x * 32;
    const int e0 = blockIdx.y * 32;
    const int b  = blockIdx.z;
    const int tx = threadIdx.x, ty = threadIdx.y;
#pragma unroll
    for (int i = 0; i < 32; i += 8)
        tile[ty + i][tx] = g_v[(size_t)(b * Tt + t0 + ty + i) * Ee + e0 + tx];
    __syncthreads();
#pragma unroll
    for (int i = 0; i < 32; i += 8) {
        int e = e0 + ty + i;
        g_vt[((size_t)(b * Hh + (e >> 6)) * DhD + (e & 63)) * Tt + t0 + tx] =
            __float2half_rn(tile[tx][ty + i]);
    }
}

// ---------------- 4) scores via mma -> fp16 S ----------------
__global__ __launch_bounds__(256)
void scores_mma_kernel()
{
    const int s0 = blockIdx.x * 128;
    const int t0 = blockIdx.y * 128;
    if (t0 + 127 < s0) return;

    const int bh = blockIdx.z;
    const int b  = bh / Hh;
    const int hh = bh % Hh;
    __half* S = g_att + (size_t)bh * Tt * Tt;

    __shared__ char ssm[32768];
    const uint32_t sa = smem_u32(ssm);
    const uint32_t sb = sa + 16384;
    const int tid  = threadIdx.x;
    const int wid  = tid >> 5;
    const int lane = tid & 31;
    const int wm = wid >> 2;
    const int wn = wid & 3;

    const __half* qbase = g_qkh + (size_t)(b * Tt) * 1536 + hh * DhD;
    const __half* kbase = qbase + 768;
#pragma unroll
    for (int it = 0; it < 4; it++) {
        int task = tid + it * 256;
        int row  = task >> 3;
        int seg  = task & 7;
        cp16(sa + SWZ(row * 128 + seg * 16), qbase + (size_t)(t0 + row) * 1536 + seg * 8);
    }
#pragma unroll
    for (int it = 0; it < 4; it++) {
        int task = tid + it * 256;
        int row  = task >> 3;
        int seg  = task & 7;
        cp16(sb + SWZ(row * 128 + seg * 16), kbase + (size_t)(s0 + row) * 1536 + seg * 8);
    }
    CP_COMMIT();
    CP_WAIT0();
    __syncthreads();

    float acc[4][4][4];
#pragma unroll
    for (int i = 0; i < 4; i++)
#pragma unroll
        for (int j = 0; j < 4; j++)
#pragma unroll
            for (int q = 0; q < 4; q++) acc[i][j][q] = 0.f;

#pragma unroll
    for (int kk = 0; kk < 4; kk++) {
        uint32_t afr[4][4];
#pragma unroll
        for (int i = 0; i < 4; i++) {
            int row = wm * 64 + i * 16 + (lane & 15);
            uint32_t off = row * 128 + kk * 32 + (lane >> 4) * 16;
            ldm_x4(afr[i], sa + SWZ(off));
        }
        uint32_t bfr[4][2];
#pragma unroll
        for (int p = 0; p < 2; p++) {
            int rown = wn * 32 + p * 16 + ((lane >> 4) & 1) * 8 + (lane & 7);
            uint32_t off = rown * 128 + kk * 32 + ((lane >> 3) & 1) * 16;
            uint32_t r[4];
            ldm_x4(r, sb + SWZ(off));
            bfr[2*p][0] = r[0]; bfr[2*p][1] = r[1];
            bfr[2*p+1][0] = r[2]; bfr[2*p+1][1] = r[3];
        }
#pragma unroll
        for (int i = 0; i < 4; i++)
#pragma unroll
            for (int j = 0; j < 4; j++)
                mma16816(acc[i][j], afr[i], bfr[j]);
    }

    const float NEG = -INFINITY;
#pragma unroll
    for (int i = 0; i < 4; i++) {
        int ta = t0 + wm * 64 + i * 16 + (lane >> 2);
        int tb = ta + 8;
        __half* r0 = S + (size_t)ta * Tt;
        __half* r1 = S + (size_t)tb * Tt;
#pragma unroll
        for (int j = 0; j < 4; j++) {
            int s = s0 + wn * 32 + j * 8 + (lane & 3) * 2;
            __half2 v0 = __floats2half2_rn((s <= ta) ? acc[i][j][0] * 8.0f : NEG,
                                           (s + 1 <= ta) ? acc[i][j][1] * 8.0f : NEG);
            __half2 v1 = __floats2half2_rn((s <= tb) ? acc[i][j][2] * 8.0f : NEG,
                                           (s + 1 <= tb) ? acc[i][j][3] * 8.0f : NEG);
            *(__half2*)(r0 + s) = v0;
            *(__half2*)(r1 + s) = v1;
        }
    }
}

// ---------------- 5) column stats on fp16 S ----------------
__global__ __launch_bounds__(256)
void stats_kernel()
{
    const int bh = blockIdx.y;
    const int s0 = blockIdx.x * 128;
    const __half* S = g_att + (size_t)bh * Tt * Tt;
    const int tid = threadIdx.x;
    const int g = tid & 31, tq = tid >> 5;
    const int col = s0 + g * 4;

    __shared__ __align__(16) float4 red[8][32];

    float4 m4 = make_float4(-INFINITY, -INFINITY, -INFINITY, -INFINITY);
    for (int t = s0 + tq; t < Tt; t += 8) {
        const __half2* p = (const __half2*)(S + (size_t)t * Tt + col);
        float2 a = __half22float2(p[0]);
        float2 b = __half22float2(p[1]);
        m4.x = fmaxf(m4.x, a.x); m4.y = fmaxf(m4.y, a.y);
        m4.z = fmaxf(m4.z, b.x); m4.w = fmaxf(m4.w, b.y);
    }
    red[tq][g] = m4;
    __syncthreads();
    if (tq == 0) {
#pragma unroll
        for (int k = 1; k < 8; k++) {
            float4 o = red[k][g];
            m4.x = fmaxf(m4.x, o.x); m4.y = fmaxf(m4.y, o.y);
            m4.z = fmaxf(m4.z, o.z); m4.w = fmaxf(m4.w, o.w);
        }
        red[0][g] = m4;
    }
    __syncthreads();
    float4 mf = red[0][g];
    __syncthreads();

    float4 sum4 = make_float4(0.f, 0.f, 0.f, 0.f);
    for (int t = s0 + tq; t < Tt; t += 8) {
        const __half2* p = (const __half2*)(S + (size_t)t * Tt + col);
        float2 a = __half22float2(p[0]);
        float2 b = __half22float2(p[1]);
        sum4.x += expw(a.x - mf.x);
        sum4.y += expw(a.y - mf.y);
        sum4.z += expw(b.x - mf.z);
        sum4.w += expw(b.y - mf.w);
    }
    red[tq][g] = sum4;
    __syncthreads();
    if (tq == 0) {
#pragma unroll
        for (int k = 1; k < 8; k++) {
            float4 o = red[k][g];
            sum4.x += o.x; sum4.y += o.y; sum4.z += o.z; sum4.w += o.w;
        }
        size_t base = (size_t)bh * Tt + col;
        g_stat[base + 0] = make_float2(mf.x, 1.0f / sum4.x);
        g_stat[base + 1] = make_float2(mf.y, 1.0f / sum4.y);
        g_stat[base + 2] = make_float2(mf.z, 1.0f / sum4.z);
        g_stat[base + 3] = make_float2(mf.w, 1.0f / sum4.w);
    }
}

// ---------------- 6) AV on tensor pipe with fused normalize (fp16 S) ----------------
__global__ __launch_bounds__(128)
void av_mma_kernel()
{
    const int t0 = ((int)gridDim.x - 1 - (int)blockIdx.x) * 128;
    const int bh = blockIdx.y;
    const int b  = bh / Hh;
    const int hh = bh % Hh;
    const __half* S  = g_att + (size_t)bh * Tt * Tt;
    const __half* VT = g_vt + (size_t)bh * DhD * Tt;

    __shared__ __align__(128) char sA[16384];
    __shared__ __align__(128) char sB[8192];
    __shared__ __align__(16) float sm[64];
    __shared__ __align__(16) float si[64];

    const uint32_t sa = smem_u32(sA);
    const uint32_t sb = smem_u32(sB);
    const int tid = threadIdx.x;
    const int wid = tid >> 5, lane = tid & 31;
    const int wm = wid >> 1, wn = wid & 1;

    float acc[4][4][4];
#pragma unroll
    for (int i = 0; i < 4; i++)
#pragma unroll
        for (int j = 0; j < 4; j++)
#pragma unroll
            for (int q = 0; q < 4; q++) acc[i][j][q] = 0.f;

    const int nk = t0 / 64 + 2;
    for (int kt = 0; kt < nk; kt++) {
        const int s1 = kt * 64;
        __syncthreads();
        if (tid < 64) {
            float2 st = g_stat[(size_t)bh * Tt + s1 + tid];
            sm[tid] = st.x; si[tid] = st.y;
        }
#pragma unroll
        for (int it = 0; it < 4; it++) {
            int task = tid + it * 128;
            int row = task >> 3, seg = task & 7;
            cp16(sb + SWZ(row * 128 + seg * 16), VT + (size_t)row * Tt + s1 + seg * 8);
        }
        CP_COMMIT();
        __syncthreads();
#pragma unroll
        for (int i = 0; i < 16; i++) {
            int idx = tid + i * 128;
            int r = idx >> 4, fc = idx & 15;
            const __half2* p = (const __half2*)(S + (size_t)(t0 + r) * Tt + s1 + fc * 4);
            float2 va = __half22float2(p[0]);
            float2 vb = __half22float2(p[1]);
            float4 mm = *(const float4*)(sm + fc * 4);
            float4 ii = *(const float4*)(si + fc * 4);
            float w0 = expw(va.x - mm.x) * ii.x;
            float w1 = expw(va.y - mm.y) * ii.y;
            float w2 = expw(vb.x - mm.z) * ii.z;
            float w3 = expw(vb.y - mm.w) * ii.w;
            __half2 h01 = __floats2half2_rn(w0, w1);
            __half2 h23 = __floats2half2_rn(w2, w3);
            uint2 pk;
            pk.x = *(uint32_t*)&h01;
            pk.y = *(uint32_t*)&h23;
            *(uint2*)(sA + SWZ(r * 128 + fc * 8)) = pk;
        }
        CP_WAIT0();
        __syncthreads();
#pragma unroll
        for (int kk = 0; kk < 4; kk++) {
            uint32_t afr[4][4];
#pragma unroll
            for (int i = 0; i < 4; i++) {
                int row = wm * 64 + i * 16 + (lane & 15);
                uint32_t off = row * 128 + kk * 32 + (lane >> 4) * 16;
                ldm_x4(afr[i], sa + SWZ(off));
            }
            uint32_t bfr[4][2];
#pragma unroll
            for (int p = 0; p < 2; p++) {
                int rown = wn * 32 + p * 16 + ((lane >> 4) & 1) * 8 + (lane & 7);
                uint32_t off = rown * 128 + kk * 32 + ((lane >> 3) & 1) * 16;
                uint32_t r[4];
                ldm_x4(r, sb + SWZ(off));
                bfr[2*p][0] = r[0]; bfr[2*p][1] = r[1];
                bfr[2*p+1][0] = r[2]; bfr[2*p+1][1] = r[3];
            }
#pragma unroll
            for (int i = 0; i < 4; i++)
#pragma unroll
                for (int j = 0; j < 4; j++)
                    mma16816(acc[i][j], afr[i], bfr[j]);
        }
    }

#pragma unroll
    for (int i = 0; i < 4; i++) {
        int m0 = t0 + wm * 64 + i * 16 + (lane >> 2);
        __half* r0 = g_a2L + (size_t)(b * Tt + m0) * 768 + hh * DhD;
        __half* r1 = r0 + (size_t)8 * 768;
#pragma unroll
        for (int j = 0; j < 4; j++) {
            int n = wn * 32 + j * 8 + (lane & 3) * 2;
            *(__half2*)(r0 + n) = __floats2half2_rn(acc[i][j][0], acc[i][j][1]);
            *(__half2*)(r1 + n) = __floats2half2_rn(acc[i][j][2], acc[i][j][3]);
        }
    }
}

// ---------------- 8) rowZ: combine partials, gather target logit ----------------
__global__ __launch_bounds__(256)
void rowZ_kernel(const float* __restrict__ logits, const int* __restrict__ y)
{
    int r = blockIdx.x * 256 + threadIdx.x;
    if (r >= BT) return;
    const float* pz = g_partZ + (size_t)r * NBY;
    float z = 0.f;
    for (int i = 0; i < NBY; i++) z += pz[i];
    g_rowlogp[r] = logits[(size_t)r * Vv + y[r]] - logf(z);
}

__global__ __launch_bounds__(256)
void loss_reduce_kernel(float* __restrict__ loss_out)
{
    __shared__ float sm[256];
    const int tid = threadIdx.x;
    float s = 0.f;
    for (int i = tid; i < BT; i += 256) s += g_rowlogp[i];
    sm[tid] = s;
    __syncthreads();
    for (int off = 128; off > 0; off >>= 1) {
        if (tid < off) sm[tid] += sm[tid + off];
        __syncthreads();
    }
    if (tid == 0) *loss_out = -sm[0] / (float)BT;
}

// ---------------- launch ----------------
extern "C" void kernel_launch(void* const* d_in, const int* in_sizes, int n_in,
                              void* d_out, int out_size)
{
    const int*   x    = (const int*)d_in[0];
    const int*   y    = (const int*)d_in[1];
    const float* tok  = (const float*)d_in[2];
    const float* pos  = (const float*)d_in[3];
    const float* Wq   = (const float*)d_in[4];
    const float* Wk   = (const float*)d_in[5];
    const float* Wv   = (const float*)d_in[6];
    const float* Wout = (const float*)d_in[7];
    const float* bout = (const float*)d_in[8];

    float* logits = (float*)d_out;
    float* loss   = (float*)d_out + (size_t)out_size - 1;

    __half *pa2q, *pb2q, *pa2L, *pb2L, *pqkh;
    float  *pv, *ppz;
    cudaGetSymbolAddress((void**)&pa2q, g_a2q);
    cudaGetSymbolAddress((void**)&pb2q, g_b2q);
    cudaGetSymbolAddress((void**)&pa2L, g_a2L);
    cudaGetSymbolAddress((void**)&pb2L, g_b2L);
    cudaGetSymbolAddress((void**)&pqkh, g_qkh);
    cudaGetSymbolAddress((void**)&pv,   g_v);
    cudaGetSymbolAddress((void**)&ppz,  g_partZ);

    cudaFuncSetAttribute(mma_gemm_kernel, cudaFuncAttributeMaxDynamicSharedMemorySize,
                         3 * STAGE_BYTES);

    // 1) embed + split h
    embed_split_kernel<<<(BT * Ee + 255) / 256, 256>>>(x, tok, pos);
    // 2) weight conversions
    packB2q_kernel<<<(QKVN * Ee + 255) / 256, 256>>>(Wq, Wk, Wv);
    {
        dim3 grid(NPAD / 32, Ee / 32);
        dim3 blk(32, 8);
        convB_kernel<<<grid, blk>>>(Wout);
    }
    // 3) qkv (fp16 3-term, K=2304) -> q,k fp16 + v fp32; 1 tile per CTA
    {
        dim3 grid(BT / 128, QKVN / 256);
        mma_gemm_kernel<<<grid, 256, 3 * STAGE_BYTES>>>(
            pa2q, pb2q, 36, 2304, 2304, QKVN / 256, QKVN, nullptr, nullptr, 0,
            1, pqkh, pv, nullptr);
    }
    // 3c) v^T fp16
    {
        dim3 grid(Tt / 32, Ee / 32, Bb);
        dim3 blk(32, 8);
        vt_kernel<<<grid, blk>>>();
    }
    // 4) raw scores (causal -inf, fp16)
    {
        dim3 grid(Tt / 128, Tt / 128, BH);
        scores_mma_kernel<<<grid, 256>>>();
    }
    // 5) per-column (max, 1/Z)
    {
        dim3 grid(Tt / 128, BH);
        stats_kernel<<<grid, 256>>>();
    }
    // 6) o = softmax(S) @ v on tensor pipe
    {
        dim3 grid(Tt / 128, BH);
        av_mma_kernel<<<grid, 128>>>();
    }
    // 7) logits (fp16 1-term, K=768) + fused partial sumexp; persistent multi-tile
    {
        dim3 grid(BT / 128, 19);
        mma_gemm_kernel<<<grid, 256, 3 * STAGE_BYTES>>>(
            pa2L, pb2L, 12, 768, 768, NBY, Vv, bout, logits, Vv,
            0, nullptr, nullptr, ppz);
    }
    // 8) loss
    rowZ_kernel<<<(BT + 255) / 256, 256>>>(logits, y);
    loss_reduce_kernel<<<1, 256>>>(loss);
}

// round 10
// speedup vs baseline: 1.2166x; 1.2166x over previous
#include <cuda_runtime.h>
#include <cuda_fp16.h>
#include <math.h>
#include <stdint.h>

// Problem constants
#define Vv   50257
#define Tt   2048
#define Ee   768
#define Hh   12
#define DhD  64
#define Bb   2
#define BT   (Bb*Tt)      // 4096
#define BH   (Bb*Hh)      // 24
#define QKVN (3*Ee)       // 2304
#define NPAD 50432        // V padded to multiple of 128
#define NBY  (NPAD/128)   // 394 logits column tiles

// ---------------- scratch (static device globals; no runtime allocs) ----------------
__device__ __half g_att[(size_t)BH*Tt*Tt];         // 201 MB raw scores (fp16)
__device__ float  g_rowlogp[BT];
__device__ float  g_partZ[(size_t)BT*NBY];         // per-row partial sumexp
__device__ float2 g_stat[(size_t)BH*Tt];           // (m_s, 1/Z_s) per column
__device__ __half g_a2q[(size_t)BT*2304];          // h split [hi|hi|lo]
__device__ __half g_b2q[(size_t)QKVN*2304];        // Wp^T split [hi|lo|hi]
__device__ __half g_qkh[(size_t)BT*1536];          // q|k fp16
__device__ float  g_v[(size_t)BT*Ee];              // v fp32
__device__ __half g_vt[(size_t)BH*DhD*Tt];         // v^T fp16 per head
__device__ __half g_a2L[(size_t)BT*768];           // o hi
__device__ __half g_b2L[(size_t)NPAD*768];         // Wout^T hi

// ================= PTX helpers (baseline ISA only) =================
__device__ __forceinline__ uint32_t smem_u32(const void* p) {
    uint32_t a;
    asm("{ .reg .u64 t; cvta.to.shared.u64 t, %1; cvt.u32.u64 %0, t; }" : "=r"(a) : "l"(p));
    return a;
}
#define SWZ(o) ((o) ^ (((o) >> 3) & 0x70))

__device__ __forceinline__ void cp16(uint32_t dst, const void* src) {
    asm volatile("cp.async.cg.shared.global [%0], [%1], 16;" :: "r"(dst), "l"(src));
}
#define CP_COMMIT() asm volatile("cp.async.commit_group;" ::: "memory")
#define CP_WAIT1()  asm volatile("cp.async.wait_group 1;" ::: "memory")
#define CP_WAIT0()  asm volatile("cp.async.wait_group 0;" ::: "memory")

__device__ __forceinline__ void ldm_x4(uint32_t* r, uint32_t addr) {
    asm volatile("ldmatrix.sync.aligned.m8n8.x4.shared.b16 {%0,%1,%2,%3}, [%4];"
                 : "=r"(r[0]), "=r"(r[1]), "=r"(r[2]), "=r"(r[3]) : "r"(addr));
}
__device__ __forceinline__ void mma16816(float* d, const uint32_t* a, const uint32_t* b) {
    asm volatile(
        "mma.sync.aligned.m16n8k16.row.col.f32.f16.f16.f32 "
        "{%0,%1,%2,%3},{%4,%5,%6,%7},{%8,%9},{%0,%1,%2,%3};"
        : "+f"(d[0]), "+f"(d[1]), "+f"(d[2]), "+f"(d[3])
        : "r"(a[0]), "r"(a[1]), "r"(a[2]), "r"(a[3]), "r"(b[0]), "r"(b[1]));
}

// Taylor exp: ~1e-5 for |x|<=0.25; fallback __expf otherwise (handles -inf -> 0)
__device__ __forceinline__ float expw(float x) {
    if (x >= -0.25f) {
        float p = 0.041666668f;
        p = fmaf(p, x, 0.16666667f);
        p = fmaf(p, x, 0.5f);
        p = fmaf(p, x, 1.0f);
        p = fmaf(p, x, 1.0f);
        return p;
    }
    return __expf(x);
}
__device__ __forceinline__ float expw0(float x) {
    if (fabsf(x) <= 0.25f) {
        float p = 0.041666668f;
        p = fmaf(p, x, 0.16666667f);
        p = fmaf(p, x, 0.5f);
        p = fmaf(p, x, 1.0f);
        p = fmaf(p, x, 1.0f);
        return p;
    }
    return __expf(x);
}

// ---------------- 1) embed + split h to fp16 [hi|hi|lo] ----------------
__global__ void embed_split_kernel(const int* __restrict__ x,
                                   const float* __restrict__ tok,
                                   const float* __restrict__ pos)
{
    int idx = blockIdx.x * blockDim.x + threadIdx.x;
    if (idx >= BT * Ee) return;
    int e  = idx % Ee;
    int bt = idx / Ee;
    int t  = bt % Tt;
    float h = tok[(size_t)x[bt]*Ee + e] + pos[(size_t)t*Ee + e];
    __half hi = __float2half_rn(h);
    __half lo = __float2half_rn(h - __half2float(hi));
    size_t rb = (size_t)bt * 2304;
    g_a2q[rb + e]        = hi;
    g_a2q[rb + 768 + e]  = hi;
    g_a2q[rb + 1536 + e] = lo;
}

// ---------------- 2a) pack Wq/Wk/Wv -> B2q ----------------
__global__ void packB2q_kernel(const float* __restrict__ Wq,
                               const float* __restrict__ Wk,
                               const float* __restrict__ Wv)
{
    int idx = blockIdx.x * blockDim.x + threadIdx.x;
    if (idx >= QKVN * Ee) return;
    int e = idx % Ee;
    int n = idx / Ee;
    int w = n / Ee;
    int r = n % Ee;
    int h = r / DhD;
    int d = r % DhD;
    const float* W = (w == 0) ? Wq : (w == 1) ? Wk : Wv;
    float v = W[(size_t)h*Ee*DhD + (size_t)e*DhD + d];
    __half hi = __float2half_rn(v);
    __half lo = __float2half_rn(v - __half2float(hi));
    size_t rb = (size_t)n * 2304;
    g_b2q[rb + e]        = hi;
    g_b2q[rb + 768 + e]  = lo;
    g_b2q[rb + 1536 + e] = hi;
}

// ---------------- 2b) transpose Wout -> B2L ----------------
__global__ __launch_bounds__(256)
void convB_kernel(const float* __restrict__ W)
{
    __shared__ float tile[32][33];
    const int n0 = blockIdx.x * 32;
    const int k0 = blockIdx.y * 32;
    const int tx = threadIdx.x;
    const int ty = threadIdx.y;
#pragma unroll
    for (int i = 0; i < 32; i += 8) {
        int k = k0 + ty + i, n = n0 + tx;
        tile[ty + i][tx] = (n < Vv) ? W[(size_t)k * Vv + n] : 0.f;
    }
    __syncthreads();
#pragma unroll
    for (int i = 0; i < 32; i += 8) {
        int n = n0 + ty + i, k = k0 + tx;
        g_b2L[(size_t)n * 768 + k] = __float2half_rn(tile[tx][ty + i]);
    }
}

// ---------------- 3) mma GEMM: CTA 128(M) x 128(N), 4 warps 64x64, 2 CTAs/SM ----------------
// K chunks of 64 fp16; 3-stage cp.async. mode 0: float out (+bias) [+ partial sumexp].
// mode 1: QKV epilogue (q,k half; v float).
#define STAGE_BYTES 32768      // 16KB A + 16KB B

__device__ __forceinline__ void load_chunk2(uint32_t sbase, int buf,
                                            const __half* __restrict__ A2, int kcol, int ka,
                                            const __half* __restrict__ B2, int kb,
                                            int bm, int bn, int tid)
{
    uint32_t dstA = sbase + buf * STAGE_BYTES;
    uint32_t dstB = dstA + 16384;
#pragma unroll
    for (int it = 0; it < 8; it++) {
        int task = tid + it * 128;
        int row  = task >> 3;
        int seg  = task & 7;
        cp16(dstA + SWZ(row * 128 + seg * 16),
             A2 + (size_t)(bm + row) * ka + kcol + seg * 8);
    }
#pragma unroll
    for (int it = 0; it < 8; it++) {
        int task = tid + it * 128;
        int row  = task >> 3;
        int seg  = task & 7;
        cp16(dstB + SWZ(row * 128 + seg * 16),
             B2 + (size_t)(bn + row) * kb + kcol + seg * 8);
    }
}

__global__ __launch_bounds__(128, 2)
void mma_gemm_kernel(const __half* __restrict__ A2, const __half* __restrict__ B2,
                     int nchunk, int ka, int kb, int Ncols,
                     const float* __restrict__ bias, float* __restrict__ out, size_t ldc,
                     int mode, __half* __restrict__ half_out, float* __restrict__ vout,
                     float* __restrict__ partZ)
{
    extern __shared__ char smem[];
    __shared__ float sred[256];
    const uint32_t sbase = smem_u32(smem);
    const int tid  = threadIdx.x;
    const int wid  = tid >> 5;
    const int lane = tid & 31;
    const int bm = blockIdx.x * 128;
    const int bn = blockIdx.y * 128;
    const int wm = wid >> 1;      // 0..1
    const int wn = wid & 1;       // 0..1 (64-col slabs)

    float acc[4][8][4];
#pragma unroll
    for (int i = 0; i < 4; i++)
#pragma unroll
        for (int j = 0; j < 8; j++)
#pragma unroll
            for (int q = 0; q < 4; q++) acc[i][j][q] = 0.f;

    load_chunk2(sbase, 0, A2, 0,  ka, B2, kb, bm, bn, tid); CP_COMMIT();
    load_chunk2(sbase, 1, A2, 64, ka, B2, kb, bm, bn, tid); CP_COMMIT();

    for (int c = 0; c < nchunk; c++) {
        CP_WAIT1();
        __syncthreads();

        if (c + 2 < nchunk) {
            load_chunk2(sbase, (c + 2) % 3, A2, (c + 2) * 64, ka, B2, kb, bm, bn, tid);
        }
        CP_COMMIT();

        const uint32_t sa = sbase + (c % 3) * STAGE_BYTES;
        const uint32_t sb = sa + 16384;

#pragma unroll
        for (int kk = 0; kk < 4; kk++) {
            uint32_t afr[4][4];
#pragma unroll
            for (int i = 0; i < 4; i++) {
                int row = wm * 64 + i * 16 + (lane & 15);
                uint32_t off = row * 128 + kk * 32 + (lane >> 4) * 16;
                ldm_x4(afr[i], sa + SWZ(off));
            }
#pragma unroll
            for (int p = 0; p < 4; p++) {
                int rown = wn * 64 + p * 16 + ((lane >> 4) & 1) * 8 + (lane & 7);
                uint32_t off = rown * 128 + kk * 32 + ((lane >> 3) & 1) * 16;
                uint32_t r[4];
                ldm_x4(r, sb + SWZ(off));
                uint32_t b0[2] = { r[0], r[1] };
                uint32_t b1[2] = { r[2], r[3] };
#pragma unroll
                for (int i = 0; i < 4; i++) {
                    mma16816(acc[i][2*p],     afr[i], b0);
                    mma16816(acc[i][2*p + 1], afr[i], b1);
                }
            }
        }
        __syncthreads();
    }

    if (mode == 0) {
        float rs[4][2];
#pragma unroll
        for (int i = 0; i < 4; i++) { rs[i][0] = 0.f; rs[i][1] = 0.f; }
#pragma unroll
        for (int i = 0; i < 4; i++) {
            int m0 = bm + wm * 64 + i * 16 + (lane >> 2);
            float* row0 = out + (size_t)m0 * ldc;
            float* row1 = out + (size_t)(m0 + 8) * ldc;
#pragma unroll
            for (int j = 0; j < 8; j++) {
                int n = bn + wn * 64 + j * 8 + (lane & 3) * 2;
                if (n < Ncols) {
                    float v0 = acc[i][j][0] + bias[n];
                    float v2 = acc[i][j][2] + bias[n];
                    row0[n] = v0; row1[n] = v2;
                    rs[i][0] += expw0(v0); rs[i][1] += expw0(v2);
                }
                if (n + 1 < Ncols) {
                    float v1 = acc[i][j][1] + bias[n + 1];
                    float v3 = acc[i][j][3] + bias[n + 1];
                    row0[n + 1] = v1; row1[n + 1] = v3;
                    rs[i][0] += expw0(v1); rs[i][1] += expw0(v3);
                }
            }
        }
        if (partZ) {
#pragma unroll
            for (int i = 0; i < 4; i++) {
                rs[i][0] += __shfl_xor_sync(0xffffffff, rs[i][0], 1);
                rs[i][0] += __shfl_xor_sync(0xffffffff, rs[i][0], 2);
                rs[i][1] += __shfl_xor_sync(0xffffffff, rs[i][1], 1);
                rs[i][1] += __shfl_xor_sync(0xffffffff, rs[i][1], 2);
            }
            if ((lane & 3) == 0) {
                int r4 = lane >> 2;
#pragma unroll
                for (int i = 0; i < 4; i++) {
                    sred[(wm * 64 + i * 16 + r4) * 2 + wn]     = rs[i][0];
                    sred[(wm * 64 + i * 16 + 8 + r4) * 2 + wn] = rs[i][1];
                }
            }
            __syncthreads();
            float z = sred[tid * 2] + sred[tid * 2 + 1];
            partZ[(size_t)(bm + tid) * NBY + blockIdx.y] = z;
        }
    } else {
#pragma unroll
        for (int i = 0; i < 4; i++) {
            int m0 = bm + wm * 64 + i * 16 + (lane >> 2);
#pragma unroll
            for (int j = 0; j < 8; j++) {
                int n = bn + wn * 64 + j * 8 + (lane & 3) * 2;
                if (n < 1536) {
                    __half* r0 = half_out + (size_t)m0 * 1536;
                    __half* r1 = half_out + (size_t)(m0 + 8) * 1536;
                    r0[n]     = __float2half_rn(acc[i][j][0]);
                    r0[n + 1] = __float2half_rn(acc[i][j][1]);
                    r1[n]     = __float2half_rn(acc[i][j][2]);
                    r1[n + 1] = __float2half_rn(acc[i][j][3]);
                } else {
                    int nv = n - 1536;
                    float* r0 = vout + (size_t)m0 * 768;
                    float* r1 = vout + (size_t)(m0 + 8) * 768;
                    r0[nv]     = acc[i][j][0];
                    r0[nv + 1] = acc[i][j][1];
                    r1[nv]     = acc[i][j][2];
                    r1[nv + 1] = acc[i][j][3];
                }
            }
        }
    }
}

// ---------------- 3c) v^T transpose: g_v fp32 -> g_vt fp16 [bh][d][t] ----------------
__global__ __launch_bounds__(256)
void vt_kernel()
{
    __shared__ float tile[32][33];
    const int t0 = blockIdx.x * 32;
    const int e0 = blockIdx.y * 32;
    const int b  = blockIdx.z;
    const int tx = threadIdx.x, ty = threadIdx.y;
#pragma unroll
    for (int i = 0; i < 32; i += 8)
        tile[ty + i][tx] = g_v[(size_t)(b * Tt + t0 + ty + i) * Ee + e0 + tx];
    __syncthreads();
#pragma unroll
    for (int i = 0; i < 32; i += 8) {
        int e = e0 + ty + i;
        g_vt[((size_t)(b * Hh + (e >> 6)) * DhD + (e & 63)) * Tt + t0 + tx] =
            __float2half_rn(tile[tx][ty + i]);
    }
}

// ---------------- 4) scores via mma -> fp16 S ----------------
__global__ __launch_bounds__(256)
void scores_mma_kernel()
{
    const int s0 = blockIdx.x * 128;
    const int t0 = blockIdx.y * 128;
    if (t0 + 127 < s0) return;

    const int bh = blockIdx.z;
    const int b  = bh / Hh;
    const int hh = bh % Hh;
    __half* S = g_att + (size_t)bh * Tt * Tt;

    __shared__ char ssm[32768];
    const uint32_t sa = smem_u32(ssm);
    const uint32_t sb = sa + 16384;
    const int tid  = threadIdx.x;
    const int wid  = tid >> 5;
    const int lane = tid & 31;
    const int wm = wid >> 2;
    const int wn = wid & 3;

    const __half* qbase = g_qkh + (size_t)(b * Tt) * 1536 + hh * DhD;
    const __half* kbase = qbase + 768;
#pragma unroll
    for (int it = 0; it < 4; it++) {
        int task = tid + it * 256;
        int row  = task >> 3;
        int seg  = task & 7;
        cp16(sa + SWZ(row * 128 + seg * 16), qbase + (size_t)(t0 + row) * 1536 + seg * 8);
    }
#pragma unroll
    for (int it = 0; it < 4; it++) {
        int task = tid + it * 256;
        int row  = task >> 3;
        int seg  = task & 7;
        cp16(sb + SWZ(row * 128 + seg * 16), kbase + (size_t)(s0 + row) * 1536 + seg * 8);
    }
    CP_COMMIT();
    CP_WAIT0();
    __syncthreads();

    float acc[4][4][4];
#pragma unroll
    for (int i = 0; i < 4; i++)
#pragma unroll
        for (int j = 0; j < 4; j++)
#pragma unroll
            for (int q = 0; q < 4; q++) acc[i][j][q] = 0.f;

#pragma unroll
    for (int kk = 0; kk < 4; kk++) {
        uint32_t afr[4][4];
#pragma unroll
        for (int i = 0; i < 4; i++) {
            int row = wm * 64 + i * 16 + (lane & 15);
            uint32_t off = row * 128 + kk * 32 + (lane >> 4) * 16;
            ldm_x4(afr[i], sa + SWZ(off));
        }
        uint32_t bfr[4][2];
#pragma unroll
        for (int p = 0; p < 2; p++) {
            int rown = wn * 32 + p * 16 + ((lane >> 4) & 1) * 8 + (lane & 7);
            uint32_t off = rown * 128 + kk * 32 + ((lane >> 3) & 1) * 16;
            uint32_t r[4];
            ldm_x4(r, sb + SWZ(off));
            bfr[2*p][0] = r[0]; bfr[2*p][1] = r[1];
            bfr[2*p+1][0] = r[2]; bfr[2*p+1][1] = r[3];
        }
#pragma unroll
        for (int i = 0; i < 4; i++)
#pragma unroll
            for (int j = 0; j < 4; j++)
                mma16816(acc[i][j], afr[i], bfr[j]);
    }

    const float NEG = -INFINITY;
#pragma unroll
    for (int i = 0; i < 4; i++) {
        int ta = t0 + wm * 64 + i * 16 + (lane >> 2);
        int tb = ta + 8;
        __half* r0 = S + (size_t)ta * Tt;
        __half* r1 = S + (size_t)tb * Tt;
#pragma unroll
        for (int j = 0; j < 4; j++) {
            int s = s0 + wn * 32 + j * 8 + (lane & 3) * 2;
            __half2 v0 = __floats2half2_rn((s <= ta) ? acc[i][j][0] * 8.0f : NEG,
                                           (s + 1 <= ta) ? acc[i][j][1] * 8.0f : NEG);
            __half2 v1 = __floats2half2_rn((s <= tb) ? acc[i][j][2] * 8.0f : NEG,
                                           (s + 1 <= tb) ? acc[i][j][3] * 8.0f : NEG);
            *(__half2*)(r0 + s) = v0;
            *(__half2*)(r1 + s) = v1;
        }
    }
}

// ---------------- 5) column stats on fp16 S ----------------
__global__ __launch_bounds__(256)
void stats_kernel()
{
    const int bh = blockIdx.y;
    const int s0 = blockIdx.x * 128;
    const __half* S = g_att + (size_t)bh * Tt * Tt;
    const int tid = threadIdx.x;
    const int g = tid & 31, tq = tid >> 5;
    const int col = s0 + g * 4;

    __shared__ __align__(16) float4 red[8][32];

    float4 m4 = make_float4(-INFINITY, -INFINITY, -INFINITY, -INFINITY);
    for (int t = s0 + tq; t < Tt; t += 8) {
        const __half2* p = (const __half2*)(S + (size_t)t * Tt + col);
        float2 a = __half22float2(p[0]);
        float2 b = __half22float2(p[1]);
        m4.x = fmaxf(m4.x, a.x); m4.y = fmaxf(m4.y, a.y);
        m4.z = fmaxf(m4.z, b.x); m4.w = fmaxf(m4.w, b.y);
    }
    red[tq][g] = m4;
    __syncthreads();
    if (tq == 0) {
#pragma unroll
        for (int k = 1; k < 8; k++) {
            float4 o = red[k][g];
            m4.x = fmaxf(m4.x, o.x); m4.y = fmaxf(m4.y, o.y);
            m4.z = fmaxf(m4.z, o.z); m4.w = fmaxf(m4.w, o.w);
        }
        red[0][g] = m4;
    }
    __syncthreads();
    float4 mf = red[0][g];
    __syncthreads();

    float4 sum4 = make_float4(0.f, 0.f, 0.f, 0.f);
    for (int t = s0 + tq; t < Tt; t += 8) {
        const __half2* p = (const __half2*)(S + (size_t)t * Tt + col);
        float2 a = __half22float2(p[0]);
        float2 b = __half22float2(p[1]);
        sum4.x += expw(a.x - mf.x);
        sum4.y += expw(a.y - mf.y);
        sum4.z += expw(b.x - mf.z);
        sum4.w += expw(b.y - mf.w);
    }
    red[tq][g] = sum4;
    __syncthreads();
    if (tq == 0) {
#pragma unroll
        for (int k = 1; k < 8; k++) {
            float4 o = red[k][g];
            sum4.x += o.x; sum4.y += o.y; sum4.z += o.z; sum4.w += o.w;
        }
        size_t base = (size_t)bh * Tt + col;
        g_stat[base + 0] = make_float2(mf.x, 1.0f / sum4.x);
        g_stat[base + 1] = make_float2(mf.y, 1.0f / sum4.y);
        g_stat[base + 2] = make_float2(mf.z, 1.0f / sum4.z);
        g_stat[base + 3] = make_float2(mf.w, 1.0f / sum4.w);
    }
}

// ---------------- 6) AV on tensor pipe with fused normalize (fp16 S) ----------------
__global__ __launch_bounds__(128)
void av_mma_kernel()
{
    const int t0 = ((int)gridDim.x - 1 - (int)blockIdx.x) * 128;
    const int bh = blockIdx.y;
    const int b  = bh / Hh;
    const int hh = bh % Hh;
    const __half* S  = g_att + (size_t)bh * Tt * Tt;
    const __half* VT = g_vt + (size_t)bh * DhD * Tt;

    __shared__ __align__(128) char sA[16384];
    __shared__ __align__(128) char sB[8192];
    __shared__ __align__(16) float sm[64];
    __shared__ __align__(16) float si[64];

    const uint32_t sa = smem_u32(sA);
    const uint32_t sb = smem_u32(sB);
    const int tid = threadIdx.x;
    const int wid = tid >> 5, lane = tid & 31;
    const int wm = wid >> 1, wn = wid & 1;

    float acc[4][4][4];
#pragma unroll
    for (int i = 0; i < 4; i++)
#pragma unroll
        for (int j = 0; j < 4; j++)
#pragma unroll
            for (int q = 0; q < 4; q++) acc[i][j][q] = 0.f;

    const int nk = t0 / 64 + 2;
    for (int kt = 0; kt < nk; kt++) {
        const int s1 = kt * 64;
        __syncthreads();
        if (tid < 64) {
            float2 st = g_stat[(size_t)bh * Tt + s1 + tid];
            sm[tid] = st.x; si[tid] = st.y;
        }
#pragma unroll
        for (int it = 0; it < 4; it++) {
            int task = tid + it * 128;
            int row = task >> 3, seg = task & 7;
            cp16(sb + SWZ(row * 128 + seg * 16), VT + (size_t)row * Tt + s1 + seg * 8);
        }
        CP_COMMIT();
        __syncthreads();
#pragma unroll
        for (int i = 0; i < 16; i++) {
            int idx = tid + i * 128;
            int r = idx >> 4, fc = idx & 15;
            const __half2* p = (const __half2*)(S + (size_t)(t0 + r) * Tt + s1 + fc * 4);
            float2 va = __half22float2(p[0]);
            float2 vb = __half22float2(p[1]);
            float4 mm = *(const float4*)(sm + fc * 4);
            float4 ii = *(const float4*)(si + fc * 4);
            float w0 = expw(va.x - mm.x) * ii.x;
            float w1 = expw(va.y - mm.y) * ii.y;
            float w2 = expw(vb.x - mm.z) * ii.z;
            float w3 = expw(vb.y - mm.w) * ii.w;
            __half2 h01 = __floats2half2_rn(w0, w1);
            __half2 h23 = __floats2half2_rn(w2, w3);
            uint2 pk;
            pk.x = *(uint32_t*)&h01;
            pk.y = *(uint32_t*)&h23;
            *(uint2*)(sA + SWZ(r * 128 + fc * 8)) = pk;
        }
        CP_WAIT0();
        __syncthreads();
#pragma unroll
        for (int kk = 0; kk < 4; kk++) {
            uint32_t afr[4][4];
#pragma unroll
            for (int i = 0; i < 4; i++) {
                int row = wm * 64 + i * 16 + (lane & 15);
                uint32_t off = row * 128 + kk * 32 + (lane >> 4) * 16;
                ldm_x4(afr[i], sa + SWZ(off));
            }
            uint32_t bfr[4][2];
#pragma unroll
            for (int p = 0; p < 2; p++) {
                int rown = wn * 32 + p * 16 + ((lane >> 4) & 1) * 8 + (lane & 7);
                uint32_t off = rown * 128 + kk * 32 + ((lane >> 3) & 1) * 16;
                uint32_t r[4];
                ldm_x4(r, sb + SWZ(off));
                bfr[2*p][0] = r[0]; bfr[2*p][1] = r[1];
                bfr[2*p+1][0] = r[2]; bfr[2*p+1][1] = r[3];
            }
#pragma unroll
            for (int i = 0; i < 4; i++)
#pragma unroll
                for (int j = 0; j < 4; j++)
                    mma16816(acc[i][j], afr[i], bfr[j]);
        }
    }

#pragma unroll
    for (int i = 0; i < 4; i++) {
        int m0 = t0 + wm * 64 + i * 16 + (lane >> 2);
        __half* r0 = g_a2L + (size_t)(b * Tt + m0) * 768 + hh * DhD;
        __half* r1 = r0 + (size_t)8 * 768;
#pragma unroll
        for (int j = 0; j < 4; j++) {
            int n = wn * 32 + j * 8 + (lane & 3) * 2;
            *(__half2*)(r0 + n) = __floats2half2_rn(acc[i][j][0], acc[i][j][1]);
            *(__half2*)(r1 + n) = __floats2half2_rn(acc[i][j][2], acc[i][j][3]);
        }
    }
}

// ---------------- 8) rowZ: combine partials, gather target logit ----------------
__global__ __launch_bounds__(256)
void rowZ_kernel(const float* __restrict__ logits, const int* __restrict__ y)
{
    int r = blockIdx.x * 256 + threadIdx.x;
    if (r >= BT) return;
    const float* pz = g_partZ + (size_t)r * NBY;
    float z = 0.f;
    for (int i = 0; i < NBY; i++) z += pz[i];
    g_rowlogp[r] = logits[(size_t)r * Vv + y[r]] - logf(z);
}

__global__ __launch_bounds__(256)
void loss_reduce_kernel(float* __restrict__ loss_out)
{
    __shared__ float sm[256];
    const int tid = threadIdx.x;
    float s = 0.f;
    for (int i = tid; i < BT; i += 256) s += g_rowlogp[i];
    sm[tid] = s;
    __syncthreads();
    for (int off = 128; off > 0; off >>= 1) {
        if (tid < off) sm[tid] += sm[tid + off];
        __syncthreads();
    }
    if (tid == 0) *loss_out = -sm[0] / (float)BT;
}

// ---------------- launch ----------------
extern "C" void kernel_launch(void* const* d_in, const int* in_sizes, int n_in,
                              void* d_out, int out_size)
{
    const int*   x    = (const int*)d_in[0];
    const int*   y    = (const int*)d_in[1];
    const float* tok  = (const float*)d_in[2];
    const float* pos  = (const float*)d_in[3];
    const float* Wq   = (const float*)d_in[4];
    const float* Wk   = (const float*)d_in[5];
    const float* Wv   = (const float*)d_in[6];
    const float* Wout = (const float*)d_in[7];
    const float* bout = (const float*)d_in[8];

    float* logits = (float*)d_out;
    float* loss   = (float*)d_out + (size_t)out_size - 1;

    __half *pa2q, *pb2q, *pa2L, *pb2L, *pqkh;
    float  *pv, *ppz;
    cudaGetSymbolAddress((void**)&pa2q, g_a2q);
    cudaGetSymbolAddress((void**)&pb2q, g_b2q);
    cudaGetSymbolAddress((void**)&pa2L, g_a2L);
    cudaGetSymbolAddress((void**)&pb2L, g_b2L);
    cudaGetSymbolAddress((void**)&pqkh, g_qkh);
    cudaGetSymbolAddress((void**)&pv,   g_v);
    cudaGetSymbolAddress((void**)&ppz,  g_partZ);

    cudaFuncSetAttribute(mma_gemm_kernel, cudaFuncAttributeMaxDynamicSharedMemorySize,
                         3 * STAGE_BYTES);

    // 1) embed + split h
    embed_split_kernel<<<(BT * Ee + 255) / 256, 256>>>(x, tok, pos);
    // 2) weight conversions
    packB2q_kernel<<<(QKVN * Ee + 255) / 256, 256>>>(Wq, Wk, Wv);
    {
        dim3 grid(NPAD / 32, Ee / 32);
        dim3 blk(32, 8);
        convB_kernel<<<grid, blk>>>(Wout);
    }
    // 3) qkv (fp16 3-term, K=2304) -> q,k fp16 + v fp32
    {
        dim3 grid(BT / 128, QKVN / 128);
        mma_gemm_kernel<<<grid, 128, 3 * STAGE_BYTES>>>(
            pa2q, pb2q, 36, 2304, 2304, QKVN, nullptr, nullptr, 0,
            1, pqkh, pv, nullptr);
    }
    // 3c) v^T fp16
    {
        dim3 grid(Tt / 32, Ee / 32, Bb);
        dim3 blk(32, 8);
        vt_kernel<<<grid, blk>>>();
    }
    // 4) raw scores (causal -inf, fp16)
    {
        dim3 grid(Tt / 128, Tt / 128, BH);
        scores_mma_kernel<<<grid, 256>>>();
    }
    // 5) per-column (max, 1/Z)
    {
        dim3 grid(Tt / 128, BH);
        stats_kernel<<<grid, 256>>>();
    }
    // 6) o = softmax(S) @ v on tensor pipe
    {
        dim3 grid(Tt / 128, BH);
        av_mma_kernel<<<grid, 128>>>();
    }
    // 7) logits (fp16 1-term, K=768) + fused partial sumexp
    {
        dim3 grid(BT / 128, NBY);
        mma_gemm_kernel<<<grid, 128, 3 * STAGE_BYTES>>>(
            pa2L, pb2L, 12, 768, 768, Vv, bout, logits, Vv,
            0, nullptr, nullptr, ppz);
    }
    // 8) loss
    rowZ_kernel<<<(BT + 255) / 256, 256>>>(logits, y);
    loss_reduce_kernel<<<1, 256>>>(loss);
}

// round 11
// speedup vs baseline: 1.2559x; 1.0324x over previous
#include <cuda_runtime.h>
#include <cuda_fp16.h>
#include <math.h>
#include <stdint.h>

// Problem constants
#define Vv   50257
#define Tt   2048
#define Ee   768
#define Hh   12
#define DhD  64
#define Bb   2
#define BT   (Bb*Tt)      // 4096
#define BH   (Bb*Hh)      // 24
#define QKVN (3*Ee)       // 2304
#define NPAD 50432        // V padded to multiple of 128
#define NBY  (NPAD/128)   // 394 logits column tiles

// ---------------- scratch (static device globals; no runtime allocs) ----------------
__device__ __half g_att[(size_t)BH*Tt*Tt];         // 201 MB raw scores (fp16)
__device__ float  g_rowlogp[BT];
__device__ float  g_partZ[(size_t)BT*NBY];         // per-row partial sumexp
__device__ float2 g_stat[(size_t)BH*Tt];           // (m_s, 1/Z_s) per column
__device__ __half g_a2q[(size_t)BT*2304];          // h split [hi|hi|lo]
__device__ __half g_b2q[(size_t)QKVN*2304];        // Wp^T split [hi|lo|hi]
__device__ __half g_qkh[(size_t)BT*1536];          // q|k fp16
__device__ float  g_v[(size_t)BT*Ee];              // v fp32
__device__ __half g_vt[(size_t)BH*DhD*Tt];         // v^T fp16 per head
__device__ __half g_a2L[(size_t)BT*768];           // o hi
__device__ __half g_b2L[(size_t)NPAD*768];         // Wout^T hi

// ================= PTX helpers (baseline ISA only) =================
__device__ __forceinline__ uint32_t smem_u32(const void* p) {
    uint32_t a;
    asm("{ .reg .u64 t; cvta.to.shared.u64 t, %1; cvt.u32.u64 %0, t; }" : "=r"(a) : "l"(p));
    return a;
}
#define SWZ(o) ((o) ^ (((o) >> 3) & 0x70))

__device__ __forceinline__ void cp16(uint32_t dst, const void* src) {
    asm volatile("cp.async.cg.shared.global [%0], [%1], 16;" :: "r"(dst), "l"(src));
}
#define CP_COMMIT() asm volatile("cp.async.commit_group;" ::: "memory")
#define CP_WAIT1()  asm volatile("cp.async.wait_group 1;" ::: "memory")
#define CP_WAIT0()  asm volatile("cp.async.wait_group 0;" ::: "memory")

__device__ __forceinline__ void ldm_x4(uint32_t* r, uint32_t addr) {
    asm volatile("ldmatrix.sync.aligned.m8n8.x4.shared.b16 {%0,%1,%2,%3}, [%4];"
                 : "=r"(r[0]), "=r"(r[1]), "=r"(r[2]), "=r"(r[3]) : "r"(addr));
}
__device__ __forceinline__ void mma16816(float* d, const uint32_t* a, const uint32_t* b) {
    asm volatile(
        "mma.sync.aligned.m16n8k16.row.col.f32.f16.f16.f32 "
        "{%0,%1,%2,%3},{%4,%5,%6,%7},{%8,%9},{%0,%1,%2,%3};"
        : "+f"(d[0]), "+f"(d[1]), "+f"(d[2]), "+f"(d[3])
        : "r"(a[0]), "r"(a[1]), "r"(a[2]), "r"(a[3]), "r"(b[0]), "r"(b[1]));
}

// Taylor exp: ~1e-5 for |x|<=0.25; fallback __expf otherwise (handles -inf -> 0)
__device__ __forceinline__ float expw(float x) {
    if (x >= -0.25f) {
        float p = 0.041666668f;
        p = fmaf(p, x, 0.16666667f);
        p = fmaf(p, x, 0.5f);
        p = fmaf(p, x, 1.0f);
        p = fmaf(p, x, 1.0f);
        return p;
    }
    return __expf(x);
}
__device__ __forceinline__ float expw0(float x) {
    if (fabsf(x) <= 0.25f) {
        float p = 0.041666668f;
        p = fmaf(p, x, 0.16666667f);
        p = fmaf(p, x, 0.5f);
        p = fmaf(p, x, 1.0f);
        p = fmaf(p, x, 1.0f);
        return p;
    }
    return __expf(x);
}

// ---------------- 1) embed + split h to fp16 [hi|hi|lo] ----------------
__global__ void embed_split_kernel(const int* __restrict__ x,
                                   const float* __restrict__ tok,
                                   const float* __restrict__ pos)
{
    int idx = blockIdx.x * blockDim.x + threadIdx.x;
    if (idx >= BT * Ee) return;
    int e  = idx % Ee;
    int bt = idx / Ee;
    int t  = bt % Tt;
    float h = tok[(size_t)x[bt]*Ee + e] + pos[(size_t)t*Ee + e];
    __half hi = __float2half_rn(h);
    __half lo = __float2half_rn(h - __half2float(hi));
    size_t rb = (size_t)bt * 2304;
    g_a2q[rb + e]        = hi;
    g_a2q[rb + 768 + e]  = hi;
    g_a2q[rb + 1536 + e] = lo;
}

// ---------------- 2a) pack Wq/Wk/Wv -> B2q ----------------
__global__ void packB2q_kernel(const float* __restrict__ Wq,
                               const float* __restrict__ Wk,
                               const float* __restrict__ Wv)
{
    int idx = blockIdx.x * blockDim.x + threadIdx.x;
    if (idx >= QKVN * Ee) return;
    int e = idx % Ee;
    int n = idx / Ee;
    int w = n / Ee;
    int r = n % Ee;
    int h = r / DhD;
    int d = r % DhD;
    const float* W = (w == 0) ? Wq : (w == 1) ? Wk : Wv;
    float v = W[(size_t)h*Ee*DhD + (size_t)e*DhD + d];
    __half hi = __float2half_rn(v);
    __half lo = __float2half_rn(v - __half2float(hi));
    size_t rb = (size_t)n * 2304;
    g_b2q[rb + e]        = hi;
    g_b2q[rb + 768 + e]  = lo;
    g_b2q[rb + 1536 + e] = hi;
}

// ---------------- 2b) transpose Wout -> B2L ----------------
__global__ __launch_bounds__(256)
void convB_kernel(const float* __restrict__ W)
{
    __shared__ float tile[32][33];
    const int n0 = blockIdx.x * 32;
    const int k0 = blockIdx.y * 32;
    const int tx = threadIdx.x;
    const int ty = threadIdx.y;
#pragma unroll
    for (int i = 0; i < 32; i += 8) {
        int k = k0 + ty + i, n = n0 + tx;
        tile[ty + i][tx] = (n < Vv) ? W[(size_t)k * Vv + n] : 0.f;
    }
    __syncthreads();
#pragma unroll
    for (int i = 0; i < 32; i += 8) {
        int n = n0 + ty + i, k = k0 + tx;
        g_b2L[(size_t)n * 768 + k] = __float2half_rn(tile[tx][ty + i]);
    }
}

// ---------------- 3) mma GEMM: CTA 128x128, 4 warps 64x64, 2 CTAs/SM ----------------
// Compile-time K chunks / strides; 3-stage cp.async; one barrier per chunk.
#define STAGE_BYTES 32768      // 16KB A + 16KB B

template<int KA, int KB>
__device__ __forceinline__ void load_chunk2(uint32_t sbase, int buf,
                                            const __half* __restrict__ A2, int kcol,
                                            const __half* __restrict__ B2,
                                            int bm, int bn, int tid)
{
    uint32_t dstA = sbase + buf * STAGE_BYTES;
    uint32_t dstB = dstA + 16384;
#pragma unroll
    for (int it = 0; it < 8; it++) {
        int task = tid + it * 128;
        int row  = task >> 3;
        int seg  = task & 7;
        cp16(dstA + SWZ(row * 128 + seg * 16),
             A2 + (size_t)(bm + row) * KA + kcol + seg * 8);
    }
#pragma unroll
    for (int it = 0; it < 8; it++) {
        int task = tid + it * 128;
        int row  = task >> 3;
        int seg  = task & 7;
        cp16(dstB + SWZ(row * 128 + seg * 16),
             B2 + (size_t)(bn + row) * KB + kcol + seg * 8);
    }
}

template<int NCHUNK, int KA, int KB>
__global__ __launch_bounds__(128, 2)
void mma_gemm_kernel(const __half* __restrict__ A2, const __half* __restrict__ B2,
                     int Ncols,
                     const float* __restrict__ bias, float* __restrict__ out, size_t ldc,
                     int mode, __half* __restrict__ half_out, float* __restrict__ vout,
                     float* __restrict__ partZ)
{
    extern __shared__ char smem[];
    __shared__ float sred[256];
    const uint32_t sbase = smem_u32(smem);
    const int tid  = threadIdx.x;
    const int wid  = tid >> 5;
    const int lane = tid & 31;
    const int bm = blockIdx.x * 128;
    const int bn = blockIdx.y * 128;
    const int wm = wid >> 1;      // 0..1
    const int wn = wid & 1;       // 0..1 (64-col slabs)

    float acc[4][8][4];
#pragma unroll
    for (int i = 0; i < 4; i++)
#pragma unroll
        for (int j = 0; j < 8; j++)
#pragma unroll
            for (int q = 0; q < 4; q++) acc[i][j][q] = 0.f;

    load_chunk2<KA, KB>(sbase, 0, A2, 0,  B2, bm, bn, tid); CP_COMMIT();
    load_chunk2<KA, KB>(sbase, 1, A2, 64, B2, bm, bn, tid); CP_COMMIT();

#pragma unroll
    for (int c = 0; c < NCHUNK; c++) {
        CP_WAIT1();
        __syncthreads();          // all warps done with chunk c-1; chunk c resident

        if (c + 2 < NCHUNK) {
            load_chunk2<KA, KB>(sbase, (c + 2) % 3, A2, (c + 2) * 64, B2, bm, bn, tid);
        }
        CP_COMMIT();

        const uint32_t sa = sbase + (c % 3) * STAGE_BYTES;
        const uint32_t sb = sa + 16384;

#pragma unroll
        for (int kk = 0; kk < 4; kk++) {
            uint32_t afr[4][4];
#pragma unroll
            for (int i = 0; i < 4; i++) {
                int row = wm * 64 + i * 16 + (lane & 15);
                uint32_t off = row * 128 + kk * 32 + (lane >> 4) * 16;
                ldm_x4(afr[i], sa + SWZ(off));
            }
#pragma unroll
            for (int p = 0; p < 4; p++) {
                int rown = wn * 64 + p * 16 + ((lane >> 4) & 1) * 8 + (lane & 7);
                uint32_t off = rown * 128 + kk * 32 + ((lane >> 3) & 1) * 16;
                uint32_t r[4];
                ldm_x4(r, sb + SWZ(off));
                uint32_t b0[2] = { r[0], r[1] };
                uint32_t b1[2] = { r[2], r[3] };
#pragma unroll
                for (int i = 0; i < 4; i++) {
                    mma16816(acc[i][2*p],     afr[i], b0);
                    mma16816(acc[i][2*p + 1], afr[i], b1);
                }
            }
        }
    }

    if (mode == 0) {
        float rs[4][2];
#pragma unroll
        for (int i = 0; i < 4; i++) { rs[i][0] = 0.f; rs[i][1] = 0.f; }
#pragma unroll
        for (int i = 0; i < 4; i++) {
            int m0 = bm + wm * 64 + i * 16 + (lane >> 2);
            float* row0 = out + (size_t)m0 * ldc;
            float* row1 = out + (size_t)(m0 + 8) * ldc;
#pragma unroll
            for (int j = 0; j < 8; j++) {
                int n = bn + wn * 64 + j * 8 + (lane & 3) * 2;
                if (n < Ncols) {
                    float v0 = acc[i][j][0] + bias[n];
                    float v2 = acc[i][j][2] + bias[n];
                    row0[n] = v0; row1[n] = v2;
                    rs[i][0] += expw0(v0); rs[i][1] += expw0(v2);
                }
                if (n + 1 < Ncols) {
                    float v1 = acc[i][j][1] + bias[n + 1];
                    float v3 = acc[i][j][3] + bias[n + 1];
                    row0[n + 1] = v1; row1[n + 1] = v3;
                    rs[i][0] += expw0(v1); rs[i][1] += expw0(v3);
                }
            }
        }
        if (partZ) {
#pragma unroll
            for (int i = 0; i < 4; i++) {
                rs[i][0] += __shfl_xor_sync(0xffffffff, rs[i][0], 1);
                rs[i][0] += __shfl_xor_sync(0xffffffff, rs[i][0], 2);
                rs[i][1] += __shfl_xor_sync(0xffffffff, rs[i][1], 1);
                rs[i][1] += __shfl_xor_sync(0xffffffff, rs[i][1], 2);
            }
            if ((lane & 3) == 0) {
                int r4 = lane >> 2;
#pragma unroll
                for (int i = 0; i < 4; i++) {
                    sred[(wm * 64 + i * 16 + r4) * 2 + wn]     = rs[i][0];
                    sred[(wm * 64 + i * 16 + 8 + r4) * 2 + wn] = rs[i][1];
                }
            }
            __syncthreads();
            float z = sred[tid * 2] + sred[tid * 2 + 1];
            partZ[(size_t)(bm + tid) * NBY + blockIdx.y] = z;
        }
    } else {
#pragma unroll
        for (int i = 0; i < 4; i++) {
            int m0 = bm + wm * 64 + i * 16 + (lane >> 2);
#pragma unroll
            for (int j = 0; j < 8; j++) {
                int n = bn + wn * 64 + j * 8 + (lane & 3) * 2;
                if (n < 1536) {
                    __half* r0 = half_out + (size_t)m0 * 1536;
                    __half* r1 = half_out + (size_t)(m0 + 8) * 1536;
                    r0[n]     = __float2half_rn(acc[i][j][0]);
                    r0[n + 1] = __float2half_rn(acc[i][j][1]);
                    r1[n]     = __float2half_rn(acc[i][j][2]);
                    r1[n + 1] = __float2half_rn(acc[i][j][3]);
                } else {
                    int nv = n - 1536;
                    float* r0 = vout + (size_t)m0 * 768;
                    float* r1 = vout + (size_t)(m0 + 8) * 768;
                    r0[nv]     = acc[i][j][0];
                    r0[nv + 1] = acc[i][j][1];
                    r1[nv]     = acc[i][j][2];
                    r1[nv + 1] = acc[i][j][3];
                }
            }
        }
    }
}

// ---------------- 3c) v^T transpose: g_v fp32 -> g_vt fp16 [bh][d][t] ----------------
__global__ __launch_bounds__(256)
void vt_kernel()
{
    __shared__ float tile[32][33];
    const int t0 = blockIdx.x * 32;
    const int e0 = blockIdx.y * 32;
    const int b  = blockIdx.z;
    const int tx = threadIdx.x, ty = threadIdx.y;
#pragma unroll
    for (int i = 0; i < 32; i += 8)
        tile[ty + i][tx] = g_v[(size_t)(b * Tt + t0 + ty + i) * Ee + e0 + tx];
    __syncthreads();
#pragma unroll
    for (int i = 0; i < 32; i += 8) {
        int e = e0 + ty + i;
        g_vt[((size_t)(b * Hh + (e >> 6)) * DhD + (e & 63)) * Tt + t0 + tx] =
            __float2half_rn(tile[tx][ty + i]);
    }
}

// ---------------- 4) scores via mma -> fp16 S (128 threads, 2 CTAs/SM) ----------------
__global__ __launch_bounds__(128, 2)
void scores_mma_kernel()
{
    const int s0 = blockIdx.x * 128;
    const int t0 = blockIdx.y * 128;
    if (t0 + 127 < s0) return;

    const int bh = blockIdx.z;
    const int b  = bh / Hh;
    const int hh = bh % Hh;
    __half* S = g_att + (size_t)bh * Tt * Tt;

    __shared__ __align__(128) char ssm[32768];
    const uint32_t sa = smem_u32(ssm);
    const uint32_t sb = sa + 16384;
    const int tid  = threadIdx.x;
    const int wid  = tid >> 5;
    const int lane = tid & 31;
    const int wm = wid >> 1;      // 0..1
    const int wn = wid & 1;       // 0..1

    const __half* qbase = g_qkh + (size_t)(b * Tt) * 1536 + hh * DhD;
    const __half* kbase = qbase + 768;
#pragma unroll
    for (int it = 0; it < 8; it++) {
        int task = tid + it * 128;
        int row  = task >> 3;
        int seg  = task & 7;
        cp16(sa + SWZ(row * 128 + seg * 16), qbase + (size_t)(t0 + row) * 1536 + seg * 8);
    }
#pragma unroll
    for (int it = 0; it < 8; it++) {
        int task = tid + it * 128;
        int row  = task >> 3;
        int seg  = task & 7;
        cp16(sb + SWZ(row * 128 + seg * 16), kbase + (size_t)(s0 + row) * 1536 + seg * 8);
    }
    CP_COMMIT();
    CP_WAIT0();
    __syncthreads();

    float acc[4][8][4];
#pragma unroll
    for (int i = 0; i < 4; i++)
#pragma unroll
        for (int j = 0; j < 8; j++)
#pragma unroll
            for (int q = 0; q < 4; q++) acc[i][j][q] = 0.f;

#pragma unroll
    for (int kk = 0; kk < 4; kk++) {
        uint32_t afr[4][4];
#pragma unroll
        for (int i = 0; i < 4; i++) {
            int row = wm * 64 + i * 16 + (lane & 15);
            uint32_t off = row * 128 + kk * 32 + (lane >> 4) * 16;
            ldm_x4(afr[i], sa + SWZ(off));
        }
#pragma unroll
        for (int p = 0; p < 4; p++) {
            int rown = wn * 64 + p * 16 + ((lane >> 4) & 1) * 8 + (lane & 7);
            uint32_t off = rown * 128 + kk * 32 + ((lane >> 3) & 1) * 16;
            uint32_t r[4];
            ldm_x4(r, sb + SWZ(off));
            uint32_t b0[2] = { r[0], r[1] };
            uint32_t b1[2] = { r[2], r[3] };
#pragma unroll
            for (int i = 0; i < 4; i++) {
                mma16816(acc[i][2*p],     afr[i], b0);
                mma16816(acc[i][2*p + 1], afr[i], b1);
            }
        }
    }

    const float NEG = -INFINITY;
#pragma unroll
    for (int i = 0; i < 4; i++) {
        int ta = t0 + wm * 64 + i * 16 + (lane >> 2);
        int tb = ta + 8;
        __half* r0 = S + (size_t)ta * Tt;
        __half* r1 = S + (size_t)tb * Tt;
#pragma unroll
        for (int j = 0; j < 8; j++) {
            int s = s0 + wn * 64 + j * 8 + (lane & 3) * 2;
            __half2 v0 = __floats2half2_rn((s <= ta) ? acc[i][j][0] * 8.0f : NEG,
                                           (s + 1 <= ta) ? acc[i][j][1] * 8.0f : NEG);
            __half2 v1 = __floats2half2_rn((s <= tb) ? acc[i][j][2] * 8.0f : NEG,
                                           (s + 1 <= tb) ? acc[i][j][3] * 8.0f : NEG);
            *(__half2*)(r0 + s) = v0;
            *(__half2*)(r1 + s) = v1;
        }
    }
}

// ---------------- 5) column stats on fp16 S ----------------
__global__ __launch_bounds__(256)
void stats_kernel()
{
    const int bh = blockIdx.y;
    const int s0 = blockIdx.x * 128;
    const __half* S = g_att + (size_t)bh * Tt * Tt;
    const int tid = threadIdx.x;
    const int g = tid & 31, tq = tid >> 5;
    const int col = s0 + g * 4;

    __shared__ __align__(16) float4 red[8][32];

    float4 m4 = make_float4(-INFINITY, -INFINITY, -INFINITY, -INFINITY);
    for (int t = s0 + tq; t < Tt; t += 8) {
        const __half2* p = (const __half2*)(S + (size_t)t * Tt + col);
        float2 a = __half22float2(p[0]);
        float2 b = __half22float2(p[1]);
        m4.x = fmaxf(m4.x, a.x); m4.y = fmaxf(m4.y, a.y);
        m4.z = fmaxf(m4.z, b.x); m4.w = fmaxf(m4.w, b.y);
    }
    red[tq][g] = m4;
    __syncthreads();
    if (tq == 0) {
#pragma unroll
        for (int k = 1; k < 8; k++) {
            float4 o = red[k][g];
            m4.x = fmaxf(m4.x, o.x); m4.y = fmaxf(m4.y, o.y);
            m4.z = fmaxf(m4.z, o.z); m4.w = fmaxf(m4.w, o.w);
        }
        red[0][g] = m4;
    }
    __syncthreads();
    float4 mf = red[0][g];
    __syncthreads();

    float4 sum4 = make_float4(0.f, 0.f, 0.f, 0.f);
    for (int t = s0 + tq; t < Tt; t += 8) {
        const __half2* p = (const __half2*)(S + (size_t)t * Tt + col);
        float2 a = __half22float2(p[0]);
        float2 b = __half22float2(p[1]);
        sum4.x += expw(a.x - mf.x);
        sum4.y += expw(a.y - mf.y);
        sum4.z += expw(b.x - mf.z);
        sum4.w += expw(b.y - mf.w);
    }
    red[tq][g] = sum4;
    __syncthreads();
    if (tq == 0) {
#pragma unroll
        for (int k = 1; k < 8; k++) {
            float4 o = red[k][g];
            sum4.x += o.x; sum4.y += o.y; sum4.z += o.z; sum4.w += o.w;
        }
        size_t base = (size_t)bh * Tt + col;
        g_stat[base + 0] = make_float2(mf.x, 1.0f / sum4.x);
        g_stat[base + 1] = make_float2(mf.y, 1.0f / sum4.y);
        g_stat[base + 2] = make_float2(mf.z, 1.0f / sum4.z);
        g_stat[base + 3] = make_float2(mf.w, 1.0f / sum4.w);
    }
}

// ---------------- 6) AV on tensor pipe with fused normalize (fp16 S) ----------------
__global__ __launch_bounds__(128)
void av_mma_kernel()
{
    const int t0 = ((int)gridDim.x - 1 - (int)blockIdx.x) * 128;
    const int bh = blockIdx.y;
    const int b  = bh / Hh;
    const int hh = bh % Hh;
    const __half* S  = g_att + (size_t)bh * Tt * Tt;
    const __half* VT = g_vt + (size_t)bh * DhD * Tt;

    __shared__ __align__(128) char sA[16384];
    __shared__ __align__(128) char sB[8192];
    __shared__ __align__(16) float sm[64];
    __shared__ __align__(16) float si[64];

    const uint32_t sa = smem_u32(sA);
    const uint32_t sb = smem_u32(sB);
    const int tid = threadIdx.x;
    const int wid = tid >> 5, lane = tid & 31;
    const int wm = wid >> 1, wn = wid & 1;

    float acc[4][4][4];
#pragma unroll
    for (int i = 0; i < 4; i++)
#pragma unroll
        for (int j = 0; j < 4; j++)
#pragma unroll
            for (int q = 0; q < 4; q++) acc[i][j][q] = 0.f;

    const int nk = t0 / 64 + 2;
    for (int kt = 0; kt < nk; kt++) {
        const int s1 = kt * 64;
        __syncthreads();
        if (tid < 64) {
            float2 st = g_stat[(size_t)bh * Tt + s1 + tid];
            sm[tid] = st.x; si[tid] = st.y;
        }
#pragma unroll
        for (int it = 0; it < 4; it++) {
            int task = tid + it * 128;
            int row = task >> 3, seg = task & 7;
            cp16(sb + SWZ(row * 128 + seg * 16), VT + (size_t)row * Tt + s1 + seg * 8);
        }
        CP_COMMIT();
        __syncthreads();
#pragma unroll
        for (int i = 0; i < 16; i++) {
            int idx = tid + i * 128;
            int r = idx >> 4, fc = idx & 15;
            const __half2* p = (const __half2*)(S + (size_t)(t0 + r) * Tt + s1 + fc * 4);
            float2 va = __half22float2(p[0]);
            float2 vb = __half22float2(p[1]);
            float4 mm = *(const float4*)(sm + fc * 4);
            float4 ii = *(const float4*)(si + fc * 4);
            float w0 = expw(va.x - mm.x) * ii.x;
            float w1 = expw(va.y - mm.y) * ii.y;
            float w2 = expw(vb.x - mm.z) * ii.z;
            float w3 = expw(vb.y - mm.w) * ii.w;
            __half2 h01 = __floats2half2_rn(w0, w1);
            __half2 h23 = __floats2half2_rn(w2, w3);
            uint2 pk;
            pk.x = *(uint32_t*)&h01;
            pk.y = *(uint32_t*)&h23;
            *(uint2*)(sA + SWZ(r * 128 + fc * 8)) = pk;
        }
        CP_WAIT0();
        __syncthreads();
#pragma unroll
        for (int kk = 0; kk < 4; kk++) {
            uint32_t afr[4][4];
#pragma unroll
            for (int i = 0; i < 4; i++) {
                int row = wm * 64 + i * 16 + (lane & 15);
                uint32_t off = row * 128 + kk * 32 + (lane >> 4) * 16;
                ldm_x4(afr[i], sa + SWZ(off));
            }
            uint32_t bfr[4][2];
#pragma unroll
            for (int p = 0; p < 2; p++) {
                int rown = wn * 32 + p * 16 + ((lane >> 4) & 1) * 8 + (lane & 7);
                uint32_t off = rown * 128 + kk * 32 + ((lane >> 3) & 1) * 16;
                uint32_t r[4];
                ldm_x4(r, sb + SWZ(off));
                bfr[2*p][0] = r[0]; bfr[2*p][1] = r[1];
                bfr[2*p+1][0] = r[2]; bfr[2*p+1][1] = r[3];
            }
#pragma unroll
            for (int i = 0; i < 4; i++)
#pragma unroll
                for (int j = 0; j < 4; j++)
                    mma16816(acc[i][j], afr[i], bfr[j]);
        }
    }

#pragma unroll
    for (int i = 0; i < 4; i++) {
        int m0 = t0 + wm * 64 + i * 16 + (lane >> 2);
        __half* r0 = g_a2L + (size_t)(b * Tt + m0) * 768 + hh * DhD;
        __half* r1 = r0 + (size_t)8 * 768;
#pragma unroll
        for (int j = 0; j < 4; j++) {
            int n = wn * 32 + j * 8 + (lane & 3) * 2;
            *(__half2*)(r0 + n) = __floats2half2_rn(acc[i][j][0], acc[i][j][1]);
            *(__half2*)(r1 + n) = __floats2half2_rn(acc[i][j][2], acc[i][j][3]);
        }
    }
}

// ---------------- 8) rowZ: combine partials, gather target logit ----------------
__global__ __launch_bounds__(256)
void rowZ_kernel(const float* __restrict__ logits, const int* __restrict__ y)
{
    int r = blockIdx.x * 256 + threadIdx.x;
    if (r >= BT) return;
    const float* pz = g_partZ + (size_t)r * NBY;
    float z = 0.f;
    for (int i = 0; i < NBY; i++) z += pz[i];
    g_rowlogp[r] = logits[(size_t)r * Vv + y[r]] - logf(z);
}

__global__ __launch_bounds__(256)
void loss_reduce_kernel(float* __restrict__ loss_out)
{
    __shared__ float sm[256];
    const int tid = threadIdx.x;
    float s = 0.f;
    for (int i = tid; i < BT; i += 256) s += g_rowlogp[i];
    sm[tid] = s;
    __syncthreads();
    for (int off = 128; off > 0; off >>= 1) {
        if (tid < off) sm[tid] += sm[tid + off];
        __syncthreads();
    }
    if (tid == 0) *loss_out = -sm[0] / (float)BT;
}

// ---------------- launch ----------------
extern "C" void kernel_launch(void* const* d_in, const int* in_sizes, int n_in,
                              void* d_out, int out_size)
{
    const int*   x    = (const int*)d_in[0];
    const int*   y    = (const int*)d_in[1];
    const float* tok  = (const float*)d_in[2];
    const float* pos  = (const float*)d_in[3];
    const float* Wq   = (const float*)d_in[4];
    const float* Wk   = (const float*)d_in[5];
    const float* Wv   = (const float*)d_in[6];
    const float* Wout = (const float*)d_in[7];
    const float* bout = (const float*)d_in[8];

    float* logits = (float*)d_out;
    float* loss   = (float*)d_out + (size_t)out_size - 1;

    __half *pa2q, *pb2q, *pa2L, *pb2L, *pqkh;
    float  *pv, *ppz;
    cudaGetSymbolAddress((void**)&pa2q, g_a2q);
    cudaGetSymbolAddress((void**)&pb2q, g_b2q);
    cudaGetSymbolAddress((void**)&pa2L, g_a2L);
    cudaGetSymbolAddress((void**)&pb2L, g_b2L);
    cudaGetSymbolAddress((void**)&pqkh, g_qkh);
    cudaGetSymbolAddress((void**)&pv,   g_v);
    cudaGetSymbolAddress((void**)&ppz,  g_partZ);

    cudaFuncSetAttribute(mma_gemm_kernel<36, 2304, 2304>,
                         cudaFuncAttributeMaxDynamicSharedMemorySize, 3 * STAGE_BYTES);
    cudaFuncSetAttribute(mma_gemm_kernel<12, 768, 768>,
                         cudaFuncAttributeMaxDynamicSharedMemorySize, 3 * STAGE_BYTES);

    // 1) embed + split h
    embed_split_kernel<<<(BT * Ee + 255) / 256, 256>>>(x, tok, pos);
    // 2) weight conversions
    packB2q_kernel<<<(QKVN * Ee + 255) / 256, 256>>>(Wq, Wk, Wv);
    {
        dim3 grid(NPAD / 32, Ee / 32);
        dim3 blk(32, 8);
        convB_kernel<<<grid, blk>>>(Wout);
    }
    // 3) qkv (fp16 3-term, K=2304) -> q,k fp16 + v fp32
    {
        dim3 grid(BT / 128, QKVN / 128);
        mma_gemm_kernel<36, 2304, 2304><<<grid, 128, 3 * STAGE_BYTES>>>(
            pa2q, pb2q, QKVN, nullptr, nullptr, 0, 1, pqkh, pv, nullptr);
    }
    // 3c) v^T fp16
    {
        dim3 grid(Tt / 32, Ee / 32, Bb);
        dim3 blk(32, 8);
        vt_kernel<<<grid, blk>>>();
    }
    // 4) raw scores (causal -inf, fp16)
    {
        dim3 grid(Tt / 128, Tt / 128, BH);
        scores_mma_kernel<<<grid, 128>>>();
    }
    // 5) per-column (max, 1/Z)
    {
        dim3 grid(Tt / 128, BH);
        stats_kernel<<<grid, 256>>>();
    }
    // 6) o = softmax(S) @ v on tensor pipe
    {
        dim3 grid(Tt / 128, BH);
        av_mma_kernel<<<grid, 128>>>();
    }
    // 7) logits (fp16 1-term, K=768) + fused partial sumexp
    {
        dim3 grid(BT / 128, NBY);
        mma_gemm_kernel<12, 768, 768><<<grid, 128, 3 * STAGE_BYTES>>>(
            pa2L, pb2L, Vv, bout, logits, Vv, 0, nullptr, nullptr, ppz);
    }
    // 8) loss
    rowZ_kernel<<<(BT + 255) / 256, 256>>>(logits, y);
    loss_reduce_kernel<<<1, 256>>>(loss);
}

// round 12
// speedup vs baseline: 1.3752x; 1.0950x over previous
#include <cuda_runtime.h>
#include <cuda_fp16.h>
#include <math.h>
#include <stdint.h>

// Problem constants
#define Vv   50257
#define Tt   2048
#define Ee   768
#define Hh   12
#define DhD  64
#define Bb   2
#define BT   (Bb*Tt)      // 4096
#define BH   (Bb*Hh)      // 24
#define QKVN (3*Ee)       // 2304
#define NPAD 50432        // V padded to multiple of 128
#define NBY  (NPAD/128)   // 394 logits column tiles

// ---------------- scratch (static device globals; no runtime allocs) ----------------
__device__ __half g_att[(size_t)BH*Tt*Tt];         // 201 MB E = exp(scores) (fp16, 0 masked)
__device__ float  g_rowlogp[BT];
__device__ float  g_partZ[(size_t)BT*NBY];         // per-row partial sumexp (loss)
__device__ float  g_pcolZ[(size_t)BH*16*Tt];       // per-(t-tile) partial column Z
__device__ float  g_invZ[(size_t)BH*Tt];           // 1/Z per column
__device__ __half g_a2q[(size_t)BT*2304];          // h split [hi|hi|lo]
__device__ __half g_b2q[(size_t)QKVN*2304];        // Wp^T split [hi|lo|hi]
__device__ __half g_qkh[(size_t)BT*1536];          // q|k fp16
__device__ float  g_v[(size_t)BT*Ee];              // v fp32
__device__ __half g_vt[(size_t)BH*DhD*Tt];         // v^T fp16 per head
__device__ __half g_a2L[(size_t)BT*768];           // o hi
__device__ __half g_b2L[(size_t)NPAD*768];         // Wout^T hi

// ================= PTX helpers (baseline ISA only) =================
__device__ __forceinline__ uint32_t smem_u32(const void* p) {
    uint32_t a;
    asm("{ .reg .u64 t; cvta.to.shared.u64 t, %1; cvt.u32.u64 %0, t; }" : "=r"(a) : "l"(p));
    return a;
}
#define SWZ(o) ((o) ^ (((o) >> 3) & 0x70))

__device__ __forceinline__ void cp16(uint32_t dst, const void* src) {
    asm volatile("cp.async.cg.shared.global [%0], [%1], 16;" :: "r"(dst), "l"(src));
}
#define CP_COMMIT() asm volatile("cp.async.commit_group;" ::: "memory")
#define CP_WAIT1()  asm volatile("cp.async.wait_group 1;" ::: "memory")
#define CP_WAIT0()  asm volatile("cp.async.wait_group 0;" ::: "memory")

__device__ __forceinline__ void ldm_x4(uint32_t* r, uint32_t addr) {
    asm volatile("ldmatrix.sync.aligned.m8n8.x4.shared.b16 {%0,%1,%2,%3}, [%4];"
                 : "=r"(r[0]), "=r"(r[1]), "=r"(r[2]), "=r"(r[3]) : "r"(addr));
}
__device__ __forceinline__ void mma16816(float* d, const uint32_t* a, const uint32_t* b) {
    asm volatile(
        "mma.sync.aligned.m16n8k16.row.col.f32.f16.f16.f32 "
        "{%0,%1,%2,%3},{%4,%5,%6,%7},{%8,%9},{%0,%1,%2,%3};"
        : "+f"(d[0]), "+f"(d[1]), "+f"(d[2]), "+f"(d[3])
        : "r"(a[0]), "r"(a[1]), "r"(a[2]), "r"(a[3]), "r"(b[0]), "r"(b[1]));
}

// Taylor exp: ~1e-5 for |x|<=0.25; fallback __expf otherwise
__device__ __forceinline__ float expw0(float x) {
    if (fabsf(x) <= 0.25f) {
        float p = 0.041666668f;
        p = fmaf(p, x, 0.16666667f);
        p = fmaf(p, x, 0.5f);
        p = fmaf(p, x, 1.0f);
        p = fmaf(p, x, 1.0f);
        return p;
    }
    return __expf(x);
}

// ---------------- 1) embed + split h to fp16 [hi|hi|lo] ----------------
__global__ void embed_split_kernel(const int* __restrict__ x,
                                   const float* __restrict__ tok,
                                   const float* __restrict__ pos)
{
    int idx = blockIdx.x * blockDim.x + threadIdx.x;
    if (idx >= BT * Ee) return;
    int e  = idx % Ee;
    int bt = idx / Ee;
    int t  = bt % Tt;
    float h = tok[(size_t)x[bt]*Ee + e] + pos[(size_t)t*Ee + e];
    __half hi = __float2half_rn(h);
    __half lo = __float2half_rn(h - __half2float(hi));
    size_t rb = (size_t)bt * 2304;
    g_a2q[rb + e]        = hi;
    g_a2q[rb + 768 + e]  = hi;
    g_a2q[rb + 1536 + e] = lo;
}

// ---------------- 2a) pack Wq/Wk/Wv -> B2q ----------------
__global__ void packB2q_kernel(const float* __restrict__ Wq,
                               const float* __restrict__ Wk,
                               const float* __restrict__ Wv)
{
    int idx = blockIdx.x * blockDim.x + threadIdx.x;
    if (idx >= QKVN * Ee) return;
    int e = idx % Ee;
    int n = idx / Ee;
    int w = n / Ee;
    int r = n % Ee;
    int h = r / DhD;
    int d = r % DhD;
    const float* W = (w == 0) ? Wq : (w == 1) ? Wk : Wv;
    float v = W[(size_t)h*Ee*DhD + (size_t)e*DhD + d];
    __half hi = __float2half_rn(v);
    __half lo = __float2half_rn(v - __half2float(hi));
    size_t rb = (size_t)n * 2304;
    g_b2q[rb + e]        = hi;
    g_b2q[rb + 768 + e]  = lo;
    g_b2q[rb + 1536 + e] = hi;
}

// ---------------- 2b) transpose Wout -> B2L ----------------
__global__ __launch_bounds__(256)
void convB_kernel(const float* __restrict__ W)
{
    __shared__ float tile[32][33];
    const int n0 = blockIdx.x * 32;
    const int k0 = blockIdx.y * 32;
    const int tx = threadIdx.x;
    const int ty = threadIdx.y;
#pragma unroll
    for (int i = 0; i < 32; i += 8) {
        int k = k0 + ty + i, n = n0 + tx;
        tile[ty + i][tx] = (n < Vv) ? W[(size_t)k * Vv + n] : 0.f;
    }
    __syncthreads();
#pragma unroll
    for (int i = 0; i < 32; i += 8) {
        int n = n0 + ty + i, k = k0 + tx;
        g_b2L[(size_t)n * 768 + k] = __float2half_rn(tile[tx][ty + i]);
    }
}

// ---------------- 3) mma GEMM: CTA 128x128, 4 warps 64x64, 2 CTAs/SM ----------------
#define STAGE_BYTES 32768      // 16KB A + 16KB B

template<int KA, int KB>
__device__ __forceinline__ void load_chunk2(uint32_t sbase, int buf,
                                            const __half* __restrict__ A2, int kcol,
                                            const __half* __restrict__ B2,
                                            int bm, int bn, int tid)
{
    uint32_t dstA = sbase + buf * STAGE_BYTES;
    uint32_t dstB = dstA + 16384;
#pragma unroll
    for (int it = 0; it < 8; it++) {
        int task = tid + it * 128;
        int row  = task >> 3;
        int seg  = task & 7;
        cp16(dstA + SWZ(row * 128 + seg * 16),
             A2 + (size_t)(bm + row) * KA + kcol + seg * 8);
    }
#pragma unroll
    for (int it = 0; it < 8; it++) {
        int task = tid + it * 128;
        int row  = task >> 3;
        int seg  = task & 7;
        cp16(dstB + SWZ(row * 128 + seg * 16),
             B2 + (size_t)(bn + row) * KB + kcol + seg * 8);
    }
}

template<int NCHUNK, int KA, int KB>
__global__ __launch_bounds__(128, 2)
void mma_gemm_kernel(const __half* __restrict__ A2, const __half* __restrict__ B2,
                     int Ncols,
                     const float* __restrict__ bias, float* __restrict__ out, size_t ldc,
                     int mode, __half* __restrict__ half_out, float* __restrict__ vout,
                     float* __restrict__ partZ)
{
    extern __shared__ char smem[];
    __shared__ float sred[256];
    const uint32_t sbase = smem_u32(smem);
    const int tid  = threadIdx.x;
    const int wid  = tid >> 5;
    const int lane = tid & 31;
    const int bm = blockIdx.x * 128;
    const int bn = blockIdx.y * 128;
    const int wm = wid >> 1;
    const int wn = wid & 1;

    float acc[4][8][4];
#pragma unroll
    for (int i = 0; i < 4; i++)
#pragma unroll
        for (int j = 0; j < 8; j++)
#pragma unroll
            for (int q = 0; q < 4; q++) acc[i][j][q] = 0.f;

    load_chunk2<KA, KB>(sbase, 0, A2, 0,  B2, bm, bn, tid); CP_COMMIT();
    load_chunk2<KA, KB>(sbase, 1, A2, 64, B2, bm, bn, tid); CP_COMMIT();

#pragma unroll
    for (int c = 0; c < NCHUNK; c++) {
        CP_WAIT1();
        __syncthreads();

        if (c + 2 < NCHUNK) {
            load_chunk2<KA, KB>(sbase, (c + 2) % 3, A2, (c + 2) * 64, B2, bm, bn, tid);
        }
        CP_COMMIT();

        const uint32_t sa = sbase + (c % 3) * STAGE_BYTES;
        const uint32_t sb = sa + 16384;

#pragma unroll
        for (int kk = 0; kk < 4; kk++) {
            uint32_t afr[4][4];
#pragma unroll
            for (int i = 0; i < 4; i++) {
                int row = wm * 64 + i * 16 + (lane & 15);
                uint32_t off = row * 128 + kk * 32 + (lane >> 4) * 16;
                ldm_x4(afr[i], sa + SWZ(off));
            }
#pragma unroll
            for (int p = 0; p < 4; p++) {
                int rown = wn * 64 + p * 16 + ((lane >> 4) & 1) * 8 + (lane & 7);
                uint32_t off = rown * 128 + kk * 32 + ((lane >> 3) & 1) * 16;
                uint32_t r[4];
                ldm_x4(r, sb + SWZ(off));
                uint32_t b0[2] = { r[0], r[1] };
                uint32_t b1[2] = { r[2], r[3] };
#pragma unroll
                for (int i = 0; i < 4; i++) {
                    mma16816(acc[i][2*p],     afr[i], b0);
                    mma16816(acc[i][2*p + 1], afr[i], b1);
                }
            }
        }
    }

    if (mode == 0) {
        float rs[4][2];
#pragma unroll
        for (int i = 0; i < 4; i++) { rs[i][0] = 0.f; rs[i][1] = 0.f; }
#pragma unroll
        for (int i = 0; i < 4; i++) {
            int m0 = bm + wm * 64 + i * 16 + (lane >> 2);
            float* row0 = out + (size_t)m0 * ldc;
            float* row1 = out + (size_t)(m0 + 8) * ldc;
#pragma unroll
            for (int j = 0; j < 8; j++) {
                int n = bn + wn * 64 + j * 8 + (lane & 3) * 2;
                if (n < Ncols) {
                    float v0 = acc[i][j][0] + bias[n];
                    float v2 = acc[i][j][2] + bias[n];
                    row0[n] = v0; row1[n] = v2;
                    rs[i][0] += expw0(v0); rs[i][1] += expw0(v2);
                }
                if (n + 1 < Ncols) {
                    float v1 = acc[i][j][1] + bias[n + 1];
                    float v3 = acc[i][j][3] + bias[n + 1];
                    row0[n + 1] = v1; row1[n + 1] = v3;
                    rs[i][0] += expw0(v1); rs[i][1] += expw0(v3);
                }
            }
        }
        if (partZ) {
#pragma unroll
            for (int i = 0; i < 4; i++) {
                rs[i][0] += __shfl_xor_sync(0xffffffff, rs[i][0], 1);
                rs[i][0] += __shfl_xor_sync(0xffffffff, rs[i][0], 2);
                rs[i][1] += __shfl_xor_sync(0xffffffff, rs[i][1], 1);
                rs[i][1] += __shfl_xor_sync(0xffffffff, rs[i][1], 2);
            }
            if ((lane & 3) == 0) {
                int r4 = lane >> 2;
#pragma unroll
                for (int i = 0; i < 4; i++) {
                    sred[(wm * 64 + i * 16 + r4) * 2 + wn]     = rs[i][0];
                    sred[(wm * 64 + i * 16 + 8 + r4) * 2 + wn] = rs[i][1];
                }
            }
            __syncthreads();
            float z = sred[tid * 2] + sred[tid * 2 + 1];
            partZ[(size_t)(bm + tid) * NBY + blockIdx.y] = z;
        }
    } else {
#pragma unroll
        for (int i = 0; i < 4; i++) {
            int m0 = bm + wm * 64 + i * 16 + (lane >> 2);
#pragma unroll
            for (int j = 0; j < 8; j++) {
                int n = bn + wn * 64 + j * 8 + (lane & 3) * 2;
                if (n < 1536) {
                    __half* r0 = half_out + (size_t)m0 * 1536;
                    __half* r1 = half_out + (size_t)(m0 + 8) * 1536;
                    r0[n]     = __float2half_rn(acc[i][j][0]);
                    r0[n + 1] = __float2half_rn(acc[i][j][1]);
                    r1[n]     = __float2half_rn(acc[i][j][2]);
                    r1[n + 1] = __float2half_rn(acc[i][j][3]);
                } else {
                    int nv = n - 1536;
                    float* r0 = vout + (size_t)m0 * 768;
                    float* r1 = vout + (size_t)(m0 + 8) * 768;
                    r0[nv]     = acc[i][j][0];
                    r0[nv + 1] = acc[i][j][1];
                    r1[nv]     = acc[i][j][2];
                    r1[nv + 1] = acc[i][j][3];
                }
            }
        }
    }
}

// ---------------- 3c) v^T transpose: g_v fp32 -> g_vt fp16 [bh][d][t] ----------------
__global__ __launch_bounds__(256)
void vt_kernel()
{
    __shared__ float tile[32][33];
    const int t0 = blockIdx.x * 32;
    const int e0 = blockIdx.y * 32;
    const int b  = blockIdx.z;
    const int tx = threadIdx.x, ty = threadIdx.y;
#pragma unroll
    for (int i = 0; i < 32; i += 8)
        tile[ty + i][tx] = g_v[(size_t)(b * Tt + t0 + ty + i) * Ee + e0 + tx];
    __syncthreads();
#pragma unroll
    for (int i = 0; i < 32; i += 8) {
        int e = e0 + ty + i;
        g_vt[((size_t)(b * Hh + (e >> 6)) * DhD + (e & 63)) * Tt + t0 + tx] =
            __float2half_rn(tile[tx][ty + i]);
    }
}

// ---------------- 4) scores via mma -> E = exp(S) fp16 + fused column partial Z ----------------
__global__ __launch_bounds__(128, 2)
void scores_mma_kernel()
{
    const int s0 = blockIdx.x * 128;
    const int t0 = blockIdx.y * 128;
    const int bh = blockIdx.z;
    const int tid  = threadIdx.x;

    if (t0 + 127 < s0) {           // fully masked tile: contribute zero to column Z
        if (tid < 128)
            g_pcolZ[((size_t)bh * 16 + (t0 >> 7)) * Tt + s0 + tid] = 0.f;
        return;
    }

    const int b  = bh / Hh;
    const int hh = bh % Hh;
    __half* S = g_att + (size_t)bh * Tt * Tt;

    __shared__ __align__(128) char ssm[32768];
    __shared__ float scol[2][128];
    const uint32_t sa = smem_u32(ssm);
    const uint32_t sb = sa + 16384;
    const int wid  = tid >> 5;
    const int lane = tid & 31;
    const int wm = wid >> 1;
    const int wn = wid & 1;

    const __half* qbase = g_qkh + (size_t)(b * Tt) * 1536 + hh * DhD;
    const __half* kbase = qbase + 768;
#pragma unroll
    for (int it = 0; it < 8; it++) {
        int task = tid + it * 128;
        int row  = task >> 3;
        int seg  = task & 7;
        cp16(sa + SWZ(row * 128 + seg * 16), qbase + (size_t)(t0 + row) * 1536 + seg * 8);
    }
#pragma unroll
    for (int it = 0; it < 8; it++) {
        int task = tid + it * 128;
        int row  = task >> 3;
        int seg  = task & 7;
        cp16(sb + SWZ(row * 128 + seg * 16), kbase + (size_t)(s0 + row) * 1536 + seg * 8);
    }
    CP_COMMIT();
    CP_WAIT0();
    __syncthreads();

    float acc[4][8][4];
#pragma unroll
    for (int i = 0; i < 4; i++)
#pragma unroll
        for (int j = 0; j < 8; j++)
#pragma unroll
            for (int q = 0; q < 4; q++) acc[i][j][q] = 0.f;

#pragma unroll
    for (int kk = 0; kk < 4; kk++) {
        uint32_t afr[4][4];
#pragma unroll
        for (int i = 0; i < 4; i++) {
            int row = wm * 64 + i * 16 + (lane & 15);
            uint32_t off = row * 128 + kk * 32 + (lane >> 4) * 16;
            ldm_x4(afr[i], sa + SWZ(off));
        }
#pragma unroll
        for (int p = 0; p < 4; p++) {
            int rown = wn * 64 + p * 16 + ((lane >> 4) & 1) * 8 + (lane & 7);
            uint32_t off = rown * 128 + kk * 32 + ((lane >> 3) & 1) * 16;
            uint32_t r[4];
            ldm_x4(r, sb + SWZ(off));
            uint32_t b0[2] = { r[0], r[1] };
            uint32_t b1[2] = { r[2], r[3] };
#pragma unroll
            for (int i = 0; i < 4; i++) {
                mma16816(acc[i][2*p],     afr[i], b0);
                mma16816(acc[i][2*p + 1], afr[i], b1);
            }
        }
    }

    // epilogue: E = exp(8*acc) (0 masked) -> fp16 store; accumulate column partials
    float colp[8][2];
#pragma unroll
    for (int j = 0; j < 8; j++) { colp[j][0] = 0.f; colp[j][1] = 0.f; }

#pragma unroll
    for (int i = 0; i < 4; i++) {
        int ta = t0 + wm * 64 + i * 16 + (lane >> 2);
        int tb = ta + 8;
        __half* r0 = S + (size_t)ta * Tt;
        __half* r1 = S + (size_t)tb * Tt;
#pragma unroll
        for (int j = 0; j < 8; j++) {
            int s = s0 + wn * 64 + j * 8 + (lane & 3) * 2;
            float e0 = (s     <= ta) ? expw0(acc[i][j][0] * 8.0f) : 0.f;
            float e1 = (s + 1 <= ta) ? expw0(acc[i][j][1] * 8.0f) : 0.f;
            float e2 = (s     <= tb) ? expw0(acc[i][j][2] * 8.0f) : 0.f;
            float e3 = (s + 1 <= tb) ? expw0(acc[i][j][3] * 8.0f) : 0.f;
            *(__half2*)(r0 + s) = __floats2half2_rn(e0, e1);
            *(__half2*)(r1 + s) = __floats2half2_rn(e2, e3);
            colp[j][0] += e0 + e2;
            colp[j][1] += e1 + e3;
        }
    }
    // reduce across the 8 row-groups (lanes differing in bits 2..4)
#pragma unroll
    for (int j = 0; j < 8; j++)
#pragma unroll
        for (int p = 0; p < 2; p++) {
            float v = colp[j][p];
            v += __shfl_xor_sync(0xffffffff, v, 4);
            v += __shfl_xor_sync(0xffffffff, v, 8);
            v += __shfl_xor_sync(0xffffffff, v, 16);
            colp[j][p] = v;
        }
    if (lane < 4) {
#pragma unroll
        for (int j = 0; j < 8; j++) {
            scol[wm][wn * 64 + j * 8 + lane * 2]     = colp[j][0];
            scol[wm][wn * 64 + j * 8 + lane * 2 + 1] = colp[j][1];
        }
    }
    __syncthreads();
    if (tid < 128)
        g_pcolZ[((size_t)bh * 16 + (t0 >> 7)) * Tt + s0 + tid] = scol[0][tid] + scol[1][tid];
}

// ---------------- 5) invZ: sum 16 t-tile partials, invert ----------------
__global__ __launch_bounds__(256)
void invZ_kernel()
{
    int idx = blockIdx.x * 256 + threadIdx.x;
    if (idx >= BH * Tt) return;
    int bh = idx >> 11, s = idx & (Tt - 1);
    float z = 0.f;
#pragma unroll
    for (int k = 0; k < 16; k++)
        z += g_pcolZ[((size_t)bh * 16 + k) * Tt + s];
    g_invZ[idx] = 1.0f / z;
}

// ---------------- 6) AV on tensor pipe: w = E * invZ (fp16 E) ----------------
__global__ __launch_bounds__(128)
void av_mma_kernel()
{
    const int t0 = ((int)gridDim.x - 1 - (int)blockIdx.x) * 128;
    const int bh = blockIdx.y;
    const int b  = bh / Hh;
    const int hh = bh % Hh;
    const __half* S  = g_att + (size_t)bh * Tt * Tt;
    const __half* VT = g_vt + (size_t)bh * DhD * Tt;

    __shared__ __align__(128) char sA[16384];
    __shared__ __align__(128) char sB[8192];
    __shared__ __align__(16) float si[64];

    const uint32_t sa = smem_u32(sA);
    const uint32_t sb = smem_u32(sB);
    const int tid = threadIdx.x;
    const int wid = tid >> 5, lane = tid & 31;
    const int wm = wid >> 1, wn = wid & 1;

    float acc[4][4][4];
#pragma unroll
    for (int i = 0; i < 4; i++)
#pragma unroll
        for (int j = 0; j < 4; j++)
#pragma unroll
            for (int q = 0; q < 4; q++) acc[i][j][q] = 0.f;

    const int nk = t0 / 64 + 2;
    for (int kt = 0; kt < nk; kt++) {
        const int s1 = kt * 64;
        __syncthreads();
        if (tid < 64) si[tid] = g_invZ[bh * Tt + s1 + tid];
#pragma unroll
        for (int it = 0; it < 4; it++) {
            int task = tid + it * 128;
            int row = task >> 3, seg = task & 7;
            cp16(sb + SWZ(row * 128 + seg * 16), VT + (size_t)row * Tt + s1 + seg * 8);
        }
        CP_COMMIT();
        __syncthreads();
#pragma unroll
        for (int i = 0; i < 16; i++) {
            int idx = tid + i * 128;
            int r = idx >> 4, fc = idx & 15;
            const __half2* p = (const __half2*)(S + (size_t)(t0 + r) * Tt + s1 + fc * 4);
            float2 va = __half22float2(p[0]);
            float2 vb = __half22float2(p[1]);
            float4 ii = *(const float4*)(si + fc * 4);
            __half2 h01 = __floats2half2_rn(va.x * ii.x, va.y * ii.y);
            __half2 h23 = __floats2half2_rn(vb.x * ii.z, vb.y * ii.w);
            uint2 pk;
            pk.x = *(uint32_t*)&h01;
            pk.y = *(uint32_t*)&h23;
            *(uint2*)(sA + SWZ(r * 128 + fc * 8)) = pk;
        }
        CP_WAIT0();
        __syncthreads();
#pragma unroll
        for (int kk = 0; kk < 4; kk++) {
            uint32_t afr[4][4];
#pragma unroll
            for (int i = 0; i < 4; i++) {
                int row = wm * 64 + i * 16 + (lane & 15);
                uint32_t off = row * 128 + kk * 32 + (lane >> 4) * 16;
                ldm_x4(afr[i], sa + SWZ(off));
            }
            uint32_t bfr[4][2];
#pragma unroll
            for (int p = 0; p < 2; p++) {
                int rown = wn * 32 + p * 16 + ((lane >> 4) & 1) * 8 + (lane & 7);
                uint32_t off = rown * 128 + kk * 32 + ((lane >> 3) & 1) * 16;
                uint32_t r[4];
                ldm_x4(r, sb + SWZ(off));
                bfr[2*p][0] = r[0]; bfr[2*p][1] = r[1];
                bfr[2*p+1][0] = r[2]; bfr[2*p+1][1] = r[3];
            }
#pragma unroll
            for (int i = 0; i < 4; i++)
#pragma unroll
                for (int j = 0; j < 4; j++)
                    mma16816(acc[i][j], afr[i], bfr[j]);
        }
    }

#pragma unroll
    for (int i = 0; i < 4; i++) {
        int m0 = t0 + wm * 64 + i * 16 + (lane >> 2);
        __half* r0 = g_a2L + (size_t)(b * Tt + m0) * 768 + hh * DhD;
        __half* r1 = r0 + (size_t)8 * 768;
#pragma unroll
        for (int j = 0; j < 4; j++) {
            int n = wn * 32 + j * 8 + (lane & 3) * 2;
            *(__half2*)(r0 + n) = __floats2half2_rn(acc[i][j][0], acc[i][j][1]);
            *(__half2*)(r1 + n) = __floats2half2_rn(acc[i][j][2], acc[i][j][3]);
        }
    }
}

// ---------------- 8) rowZ: combine partials, gather target logit ----------------
__global__ __launch_bounds__(256)
void rowZ_kernel(const float* __restrict__ logits, const int* __restrict__ y)
{
    int r = blockIdx.x * 256 + threadIdx.x;
    if (r >= BT) return;
    const float* pz = g_partZ + (size_t)r * NBY;
    float z = 0.f;
    for (int i = 0; i < NBY; i++) z += pz[i];
    g_rowlogp[r] = logits[(size_t)r * Vv + y[r]] - logf(z);
}

__global__ __launch_bounds__(256)
void loss_reduce_kernel(float* __restrict__ loss_out)
{
    __shared__ float sm[256];
    const int tid = threadIdx.x;
    float s = 0.f;
    for (int i = tid; i < BT; i += 256) s += g_rowlogp[i];
    sm[tid] = s;
    __syncthreads();
    for (int off = 128; off > 0; off >>= 1) {
        if (tid < off) sm[tid] += sm[tid + off];
        __syncthreads();
    }
    if (tid == 0) *loss_out = -sm[0] / (float)BT;
}

// ---------------- launch ----------------
extern "C" void kernel_launch(void* const* d_in, const int* in_sizes, int n_in,
                              void* d_out, int out_size)
{
    const int*   x    = (const int*)d_in[0];
    const int*   y    = (const int*)d_in[1];
    const float* tok  = (const float*)d_in[2];
    const float* pos  = (const float*)d_in[3];
    const float* Wq   = (const float*)d_in[4];
    const float* Wk   = (const float*)d_in[5];
    const float* Wv   = (const float*)d_in[6];
    const float* Wout = (const float*)d_in[7];
    const float* bout = (const float*)d_in[8];

    float* logits = (float*)d_out;
    float* loss   = (float*)d_out + (size_t)out_size - 1;

    __half *pa2q, *pb2q, *pa2L, *pb2L, *pqkh;
    float  *pv, *ppz;
    cudaGetSymbolAddress((void**)&pa2q, g_a2q);
    cudaGetSymbolAddress((void**)&pb2q, g_b2q);
    cudaGetSymbolAddress((void**)&pa2L, g_a2L);
    cudaGetSymbolAddress((void**)&pb2L, g_b2L);
    cudaGetSymbolAddress((void**)&pqkh, g_qkh);
    cudaGetSymbolAddress((void**)&pv,   g_v);
    cudaGetSymbolAddress((void**)&ppz,  g_partZ);

    cudaFuncSetAttribute(mma_gemm_kernel<36, 2304, 2304>,
                         cudaFuncAttributeMaxDynamicSharedMemorySize, 3 * STAGE_BYTES);
    cudaFuncSetAttribute(mma_gemm_kernel<12, 768, 768>,
                         cudaFuncAttributeMaxDynamicSharedMemorySize, 3 * STAGE_BYTES);

    // 1) embed + split h
    embed_split_kernel<<<(BT * Ee + 255) / 256, 256>>>(x, tok, pos);
    // 2) weight conversions
    packB2q_kernel<<<(QKVN * Ee + 255) / 256, 256>>>(Wq, Wk, Wv);
    {
        dim3 grid(NPAD / 32, Ee / 32);
        dim3 blk(32, 8);
        convB_kernel<<<grid, blk>>>(Wout);
    }
    // 3) qkv (fp16 3-term, K=2304) -> q,k fp16 + v fp32
    {
        dim3 grid(BT / 128, QKVN / 128);
        mma_gemm_kernel<36, 2304, 2304><<<grid, 128, 3 * STAGE_BYTES>>>(
            pa2q, pb2q, QKVN, nullptr, nullptr, 0, 1, pqkh, pv, nullptr);
    }
    // 3c) v^T fp16
    {
        dim3 grid(Tt / 32, Ee / 32, Bb);
        dim3 blk(32, 8);
        vt_kernel<<<grid, blk>>>();
    }
    // 4) E = exp(scores) fp16 + per-tile column partial Z
    {
        dim3 grid(Tt / 128, Tt / 128, BH);
        scores_mma_kernel<<<grid, 128>>>();
    }
    // 5) invZ per column
    invZ_kernel<<<(BH * Tt + 255) / 256, 256>>>();
    // 6) o = (E * invZ) @ v on tensor pipe
    {
        dim3 grid(Tt / 128, BH);
        av_mma_kernel<<<grid, 128>>>();
    }
    // 7) logits (fp16 1-term, K=768) + fused partial sumexp
    {
        dim3 grid(BT / 128, NBY);
        mma_gemm_kernel<12, 768, 768><<<grid, 128, 3 * STAGE_BYTES>>>(
            pa2L, pb2L, Vv, bout, logits, Vv, 0, nullptr, nullptr, ppz);
    }
    // 8) loss
    rowZ_kernel<<<(BT + 255) / 256, 256>>>(logits, y);
    loss_reduce_kernel<<<1, 256>>>(loss);
}

// round 13
// speedup vs baseline: 1.4621x; 1.0632x over previous
#include <cuda_runtime.h>
#include <cuda_fp16.h>
#include <math.h>
#include <stdint.h>

// Problem constants
#define Vv   50257
#define Tt   2048
#define Ee   768
#define Hh   12
#define DhD  64
#define Bb   2
#define BT   (Bb*Tt)      // 4096
#define BH   (Bb*Hh)      // 24
#define QKVN (3*Ee)       // 2304
#define NPAD 50432        // V padded to multiple of 128
#define NBY  (NPAD/128)   // 394 logits column tiles

// ---------------- scratch (static device globals; no runtime allocs) ----------------
__device__ __half g_att[(size_t)BH*Tt*Tt];         // 201 MB E = exp(scores) (fp16, 0 masked)
__device__ float  g_rowlogp[BT];
__device__ float  g_partZ[(size_t)BT*NBY];         // per-row partial sumexp (loss)
__device__ float  g_pcolZ[(size_t)BH*16*Tt];       // per-(t-tile) partial column Z
__device__ float  g_invZ[(size_t)BH*Tt];           // 1/Z per column
__device__ __half g_a2q[(size_t)BT*2304];          // h split [hi|hi|lo]
__device__ __half g_b2q[(size_t)QKVN*2304];        // Wp^T split [hi|lo|hi]
__device__ __half g_qkh[(size_t)BT*1536];          // q|k fp16
__device__ float  g_v[(size_t)BT*Ee];              // v fp32
__device__ __half g_vt[(size_t)BH*DhD*Tt];         // (invZ * v)^T fp16 per head
__device__ __half g_a2L[(size_t)BT*768];           // o hi
__device__ __half g_b2L[(size_t)NPAD*768];         // Wout^T hi

// ================= PTX helpers (baseline ISA only) =================
__device__ __forceinline__ uint32_t smem_u32(const void* p) {
    uint32_t a;
    asm("{ .reg .u64 t; cvta.to.shared.u64 t, %1; cvt.u32.u64 %0, t; }" : "=r"(a) : "l"(p));
    return a;
}
#define SWZ(o) ((o) ^ (((o) >> 3) & 0x70))

__device__ __forceinline__ void cp16(uint32_t dst, const void* src) {
    asm volatile("cp.async.cg.shared.global [%0], [%1], 16;" :: "r"(dst), "l"(src));
}
#define CP_COMMIT() asm volatile("cp.async.commit_group;" ::: "memory")
#define CP_WAIT1()  asm volatile("cp.async.wait_group 1;" ::: "memory")
#define CP_WAIT0()  asm volatile("cp.async.wait_group 0;" ::: "memory")

__device__ __forceinline__ void ldm_x4(uint32_t* r, uint32_t addr) {
    asm volatile("ldmatrix.sync.aligned.m8n8.x4.shared.b16 {%0,%1,%2,%3}, [%4];"
                 : "=r"(r[0]), "=r"(r[1]), "=r"(r[2]), "=r"(r[3]) : "r"(addr));
}
__device__ __forceinline__ void mma16816(float* d, const uint32_t* a, const uint32_t* b) {
    asm volatile(
        "mma.sync.aligned.m16n8k16.row.col.f32.f16.f16.f32 "
        "{%0,%1,%2,%3},{%4,%5,%6,%7},{%8,%9},{%0,%1,%2,%3};"
        : "+f"(d[0]), "+f"(d[1]), "+f"(d[2]), "+f"(d[3])
        : "r"(a[0]), "r"(a[1]), "r"(a[2]), "r"(a[3]), "r"(b[0]), "r"(b[1]));
}

// Taylor exp: ~1e-5 for |x|<=0.25; fallback __expf otherwise
__device__ __forceinline__ float expw0(float x) {
    if (fabsf(x) <= 0.25f) {
        float p = 0.041666668f;
        p = fmaf(p, x, 0.16666667f);
        p = fmaf(p, x, 0.5f);
        p = fmaf(p, x, 1.0f);
        p = fmaf(p, x, 1.0f);
        return p;
    }
    return __expf(x);
}

// ---------------- 1) embed + split h to fp16 [hi|hi|lo] ----------------
__global__ void embed_split_kernel(const int* __restrict__ x,
                                   const float* __restrict__ tok,
                                   const float* __restrict__ pos)
{
    int idx = blockIdx.x * blockDim.x + threadIdx.x;
    if (idx >= BT * Ee) return;
    int e  = idx % Ee;
    int bt = idx / Ee;
    int t  = bt % Tt;
    float h = tok[(size_t)x[bt]*Ee + e] + pos[(size_t)t*Ee + e];
    __half hi = __float2half_rn(h);
    __half lo = __float2half_rn(h - __half2float(hi));
    size_t rb = (size_t)bt * 2304;
    g_a2q[rb + e]        = hi;
    g_a2q[rb + 768 + e]  = hi;
    g_a2q[rb + 1536 + e] = lo;
}

// ---------------- 2a) pack Wq/Wk/Wv -> B2q ----------------
__global__ void packB2q_kernel(const float* __restrict__ Wq,
                               const float* __restrict__ Wk,
                               const float* __restrict__ Wv)
{
    int idx = blockIdx.x * blockDim.x + threadIdx.x;
    if (idx >= QKVN * Ee) return;
    int e = idx % Ee;
    int n = idx / Ee;
    int w = n / Ee;
    int r = n % Ee;
    int h = r / DhD;
    int d = r % DhD;
    const float* W = (w == 0) ? Wq : (w == 1) ? Wk : Wv;
    float v = W[(size_t)h*Ee*DhD + (size_t)e*DhD + d];
    __half hi = __float2half_rn(v);
    __half lo = __float2half_rn(v - __half2float(hi));
    size_t rb = (size_t)n * 2304;
    g_b2q[rb + e]        = hi;
    g_b2q[rb + 768 + e]  = lo;
    g_b2q[rb + 1536 + e] = hi;
}

// ---------------- 2b) transpose Wout -> B2L ----------------
__global__ __launch_bounds__(256)
void convB_kernel(const float* __restrict__ W)
{
    __shared__ float tile[32][33];
    const int n0 = blockIdx.x * 32;
    const int k0 = blockIdx.y * 32;
    const int tx = threadIdx.x;
    const int ty = threadIdx.y;
#pragma unroll
    for (int i = 0; i < 32; i += 8) {
        int k = k0 + ty + i, n = n0 + tx;
        tile[ty + i][tx] = (n < Vv) ? W[(size_t)k * Vv + n] : 0.f;
    }
    __syncthreads();
#pragma unroll
    for (int i = 0; i < 32; i += 8) {
        int n = n0 + ty + i, k = k0 + tx;
        g_b2L[(size_t)n * 768 + k] = __float2half_rn(tile[tx][ty + i]);
    }
}

// ---------------- 3) mma GEMM: CTA 128x128, 4 warps 64x64, 2 CTAs/SM ----------------
#define STAGE_BYTES 32768      // 16KB A + 16KB B

template<int KA, int KB>
__device__ __forceinline__ void load_chunk2(uint32_t sbase, int buf,
                                            const __half* __restrict__ A2, int kcol,
                                            const __half* __restrict__ B2,
                                            int bm, int bn, int tid)
{
    uint32_t dstA = sbase + buf * STAGE_BYTES;
    uint32_t dstB = dstA + 16384;
#pragma unroll
    for (int it = 0; it < 8; it++) {
        int task = tid + it * 128;
        int row  = task >> 3;
        int seg  = task & 7;
        cp16(dstA + SWZ(row * 128 + seg * 16),
             A2 + (size_t)(bm + row) * KA + kcol + seg * 8);
    }
#pragma unroll
    for (int it = 0; it < 8; it++) {
        int task = tid + it * 128;
        int row  = task >> 3;
        int seg  = task & 7;
        cp16(dstB + SWZ(row * 128 + seg * 16),
             B2 + (size_t)(bn + row) * KB + kcol + seg * 8);
    }
}

template<int NCHUNK, int KA, int KB>
__global__ __launch_bounds__(128, 2)
void mma_gemm_kernel(const __half* __restrict__ A2, const __half* __restrict__ B2,
                     int Ncols,
                     const float* __restrict__ bias, float* __restrict__ out, size_t ldc,
                     int mode, __half* __restrict__ half_out, float* __restrict__ vout,
                     float* __restrict__ partZ)
{
    extern __shared__ char smem[];
    __shared__ float sred[256];
    const uint32_t sbase = smem_u32(smem);
    const int tid  = threadIdx.x;
    const int wid  = tid >> 5;
    const int lane = tid & 31;
    const int bm = blockIdx.x * 128;
    const int bn = blockIdx.y * 128;
    const int wm = wid >> 1;
    const int wn = wid & 1;

    float acc[4][8][4];
#pragma unroll
    for (int i = 0; i < 4; i++)
#pragma unroll
        for (int j = 0; j < 8; j++)
#pragma unroll
            for (int q = 0; q < 4; q++) acc[i][j][q] = 0.f;

    load_chunk2<KA, KB>(sbase, 0, A2, 0,  B2, bm, bn, tid); CP_COMMIT();
    load_chunk2<KA, KB>(sbase, 1, A2, 64, B2, bm, bn, tid); CP_COMMIT();

#pragma unroll
    for (int c = 0; c < NCHUNK; c++) {
        CP_WAIT1();
        __syncthreads();

        if (c + 2 < NCHUNK) {
            load_chunk2<KA, KB>(sbase, (c + 2) % 3, A2, (c + 2) * 64, B2, bm, bn, tid);
        }
        CP_COMMIT();

        const uint32_t sa = sbase + (c % 3) * STAGE_BYTES;
        const uint32_t sb = sa + 16384;

#pragma unroll
        for (int kk = 0; kk < 4; kk++) {
            uint32_t afr[4][4];
#pragma unroll
            for (int i = 0; i < 4; i++) {
                int row = wm * 64 + i * 16 + (lane & 15);
                uint32_t off = row * 128 + kk * 32 + (lane >> 4) * 16;
                ldm_x4(afr[i], sa + SWZ(off));
            }
#pragma unroll
            for (int p = 0; p < 4; p++) {
                int rown = wn * 64 + p * 16 + ((lane >> 4) & 1) * 8 + (lane & 7);
                uint32_t off = rown * 128 + kk * 32 + ((lane >> 3) & 1) * 16;
                uint32_t r[4];
                ldm_x4(r, sb + SWZ(off));
                uint32_t b0[2] = { r[0], r[1] };
                uint32_t b1[2] = { r[2], r[3] };
#pragma unroll
                for (int i = 0; i < 4; i++) {
                    mma16816(acc[i][2*p],     afr[i], b0);
                    mma16816(acc[i][2*p + 1], afr[i], b1);
                }
            }
        }
    }

    if (mode == 0) {
        float rs[4][2];
#pragma unroll
        for (int i = 0; i < 4; i++) { rs[i][0] = 0.f; rs[i][1] = 0.f; }
#pragma unroll
        for (int i = 0; i < 4; i++) {
            int m0 = bm + wm * 64 + i * 16 + (lane >> 2);
            float* row0 = out + (size_t)m0 * ldc;
            float* row1 = out + (size_t)(m0 + 8) * ldc;
#pragma unroll
            for (int j = 0; j < 8; j++) {
                int n = bn + wn * 64 + j * 8 + (lane & 3) * 2;
                if (n < Ncols) {
                    float v0 = acc[i][j][0] + bias[n];
                    float v2 = acc[i][j][2] + bias[n];
                    row0[n] = v0; row1[n] = v2;
                    rs[i][0] += expw0(v0); rs[i][1] += expw0(v2);
                }
                if (n + 1 < Ncols) {
                    float v1 = acc[i][j][1] + bias[n + 1];
                    float v3 = acc[i][j][3] + bias[n + 1];
                    row0[n + 1] = v1; row1[n + 1] = v3;
                    rs[i][0] += expw0(v1); rs[i][1] += expw0(v3);
                }
            }
        }
        if (partZ) {
#pragma unroll
            for (int i = 0; i < 4; i++) {
                rs[i][0] += __shfl_xor_sync(0xffffffff, rs[i][0], 1);
                rs[i][0] += __shfl_xor_sync(0xffffffff, rs[i][0], 2);
                rs[i][1] += __shfl_xor_sync(0xffffffff, rs[i][1], 1);
                rs[i][1] += __shfl_xor_sync(0xffffffff, rs[i][1], 2);
            }
            if ((lane & 3) == 0) {
                int r4 = lane >> 2;
#pragma unroll
                for (int i = 0; i < 4; i++) {
                    sred[(wm * 64 + i * 16 + r4) * 2 + wn]     = rs[i][0];
                    sred[(wm * 64 + i * 16 + 8 + r4) * 2 + wn] = rs[i][1];
                }
            }
            __syncthreads();
            float z = sred[tid * 2] + sred[tid * 2 + 1];
            partZ[(size_t)(bm + tid) * NBY + blockIdx.y] = z;
        }
    } else {
#pragma unroll
        for (int i = 0; i < 4; i++) {
            int m0 = bm + wm * 64 + i * 16 + (lane >> 2);
#pragma unroll
            for (int j = 0; j < 8; j++) {
                int n = bn + wn * 64 + j * 8 + (lane & 3) * 2;
                if (n < 1536) {
                    __half* r0 = half_out + (size_t)m0 * 1536;
                    __half* r1 = half_out + (size_t)(m0 + 8) * 1536;
                    r0[n]     = __float2half_rn(acc[i][j][0]);
                    r0[n + 1] = __float2half_rn(acc[i][j][1]);
                    r1[n]     = __float2half_rn(acc[i][j][2]);
                    r1[n + 1] = __float2half_rn(acc[i][j][3]);
                } else {
                    int nv = n - 1536;
                    float* r0 = vout + (size_t)m0 * 768;
                    float* r1 = vout + (size_t)(m0 + 8) * 768;
                    r0[nv]     = acc[i][j][0];
                    r0[nv + 1] = acc[i][j][1];
                    r1[nv]     = acc[i][j][2];
                    r1[nv + 1] = acc[i][j][3];
                }
            }
        }
    }
}

// ---------------- 3c) v^T transpose + invZ fold: g_vt = (invZ[s] * v[s,d])^T fp16 ----------------
__global__ __launch_bounds__(256)
void vt_kernel()
{
    __shared__ float tile[32][33];
    const int t0 = blockIdx.x * 32;
    const int e0 = blockIdx.y * 32;
    const int b  = blockIdx.z;
    const int tx = threadIdx.x, ty = threadIdx.y;
#pragma unroll
    for (int i = 0; i < 32; i += 8)
        tile[ty + i][tx] = g_v[(size_t)(b * Tt + t0 + ty + i) * Ee + e0 + tx];
    __syncthreads();
#pragma unroll
    for (int i = 0; i < 32; i += 8) {
        int e = e0 + ty + i;
        int bh = b * Hh + (e >> 6);
        float iz = g_invZ[(size_t)bh * Tt + t0 + tx];
        g_vt[((size_t)bh * DhD + (e & 63)) * Tt + t0 + tx] =
            __float2half_rn(tile[tx][ty + i] * iz);
    }
}

// ---------------- 4) scores via mma -> E = exp(S) fp16 + fused column partial Z ----------------
__global__ __launch_bounds__(128, 2)
void scores_mma_kernel()
{
    const int s0 = blockIdx.x * 128;
    const int t0 = blockIdx.y * 128;
    const int bh = blockIdx.z;
    const int tid  = threadIdx.x;

    if (t0 + 127 < s0) {           // fully masked tile: contribute zero to column Z
        if (tid < 128)
            g_pcolZ[((size_t)bh * 16 + (t0 >> 7)) * Tt + s0 + tid] = 0.f;
        return;
    }

    const int b  = bh / Hh;
    const int hh = bh % Hh;
    __half* S = g_att + (size_t)bh * Tt * Tt;

    __shared__ __align__(128) char ssm[32768];
    __shared__ float scol[2][128];
    const uint32_t sa = smem_u32(ssm);
    const uint32_t sb = sa + 16384;
    const int wid  = tid >> 5;
    const int lane = tid & 31;
    const int wm = wid >> 1;
    const int wn = wid & 1;

    const __half* qbase = g_qkh + (size_t)(b * Tt) * 1536 + hh * DhD;
    const __half* kbase = qbase + 768;
#pragma unroll
    for (int it = 0; it < 8; it++) {
        int task = tid + it * 128;
        int row  = task >> 3;
        int seg  = task & 7;
        cp16(sa + SWZ(row * 128 + seg * 16), qbase + (size_t)(t0 + row) * 1536 + seg * 8);
    }
#pragma unroll
    for (int it = 0; it < 8; it++) {
        int task = tid + it * 128;
        int row  = task >> 3;
        int seg  = task & 7;
        cp16(sb + SWZ(row * 128 + seg * 16), kbase + (size_t)(s0 + row) * 1536 + seg * 8);
    }
    CP_COMMIT();
    CP_WAIT0();
    __syncthreads();

    float acc[4][8][4];
#pragma unroll
    for (int i = 0; i < 4; i++)
#pragma unroll
        for (int j = 0; j < 8; j++)
#pragma unroll
            for (int q = 0; q < 4; q++) acc[i][j][q] = 0.f;

#pragma unroll
    for (int kk = 0; kk < 4; kk++) {
        uint32_t afr[4][4];
#pragma unroll
        for (int i = 0; i < 4; i++) {
            int row = wm * 64 + i * 16 + (lane & 15);
            uint32_t off = row * 128 + kk * 32 + (lane >> 4) * 16;
            ldm_x4(afr[i], sa + SWZ(off));
        }
#pragma unroll
        for (int p = 0; p < 4; p++) {
            int rown = wn * 64 + p * 16 + ((lane >> 4) & 1) * 8 + (lane & 7);
            uint32_t off = rown * 128 + kk * 32 + ((lane >> 3) & 1) * 16;
            uint32_t r[4];
            ldm_x4(r, sb + SWZ(off));
            uint32_t b0[2] = { r[0], r[1] };
            uint32_t b1[2] = { r[2], r[3] };
#pragma unroll
            for (int i = 0; i < 4; i++) {
                mma16816(acc[i][2*p],     afr[i], b0);
                mma16816(acc[i][2*p + 1], afr[i], b1);
            }
        }
    }

    // epilogue: E = exp(8*acc) (0 masked) -> fp16 store; accumulate column partials
    float colp[8][2];
#pragma unroll
    for (int j = 0; j < 8; j++) { colp[j][0] = 0.f; colp[j][1] = 0.f; }

#pragma unroll
    for (int i = 0; i < 4; i++) {
        int ta = t0 + wm * 64 + i * 16 + (lane >> 2);
        int tb = ta + 8;
        __half* r0 = S + (size_t)ta * Tt;
        __half* r1 = S + (size_t)tb * Tt;
#pragma unroll
        for (int j = 0; j < 8; j++) {
            int s = s0 + wn * 64 + j * 8 + (lane & 3) * 2;
            float e0 = (s     <= ta) ? expw0(acc[i][j][0] * 8.0f) : 0.f;
            float e1 = (s + 1 <= ta) ? expw0(acc[i][j][1] * 8.0f) : 0.f;
            float e2 = (s     <= tb) ? expw0(acc[i][j][2] * 8.0f) : 0.f;
            float e3 = (s + 1 <= tb) ? expw0(acc[i][j][3] * 8.0f) : 0.f;
            *(__half2*)(r0 + s) = __floats2half2_rn(e0, e1);
            *(__half2*)(r1 + s) = __floats2half2_rn(e2, e3);
            colp[j][0] += e0 + e2;
            colp[j][1] += e1 + e3;
        }
    }
#pragma unroll
    for (int j = 0; j < 8; j++)
#pragma unroll
        for (int p = 0; p < 2; p++) {
            float v = colp[j][p];
            v += __shfl_xor_sync(0xffffffff, v, 4);
            v += __shfl_xor_sync(0xffffffff, v, 8);
            v += __shfl_xor_sync(0xffffffff, v, 16);
            colp[j][p] = v;
        }
    if (lane < 4) {
#pragma unroll
        for (int j = 0; j < 8; j++) {
            scol[wm][wn * 64 + j * 8 + lane * 2]     = colp[j][0];
            scol[wm][wn * 64 + j * 8 + lane * 2 + 1] = colp[j][1];
        }
    }
    __syncthreads();
    if (tid < 128)
        g_pcolZ[((size_t)bh * 16 + (t0 >> 7)) * Tt + s0 + tid] = scol[0][tid] + scol[1][tid];
}

// ---------------- 5) invZ: sum 16 t-tile partials, invert ----------------
__global__ __launch_bounds__(256)
void invZ_kernel()
{
    int idx = blockIdx.x * 256 + threadIdx.x;
    if (idx >= BH * Tt) return;
    int bh = idx >> 11, s = idx & (Tt - 1);
    float z = 0.f;
#pragma unroll
    for (int k = 0; k < 16; k++)
        z += g_pcolZ[((size_t)bh * 16 + k) * Tt + s];
    g_invZ[idx] = 1.0f / z;
}

// ---------------- 6) AV: pure pipelined GEMM o = E @ (invZ*V) ----------------
// CTA 128(t) x 64(d), 4 warps 64x32; K over s in 64-chunks (causal bound), 3-stage cp.async.
#define AV_STAGE 24576   // 16KB A (E) + 8KB B (VT)

__device__ __forceinline__ void av_load_chunk(uint32_t sbase, int buf,
                                              const __half* __restrict__ S, int t0,
                                              const __half* __restrict__ VT,
                                              int s1, int tid)
{
    uint32_t dstA = sbase + buf * AV_STAGE;
    uint32_t dstB = dstA + 16384;
#pragma unroll
    for (int it = 0; it < 8; it++) {
        int task = tid + it * 128;
        int row  = task >> 3;
        int seg  = task & 7;
        cp16(dstA + SWZ(row * 128 + seg * 16),
             S + (size_t)(t0 + row) * Tt + s1 + seg * 8);
    }
#pragma unroll
    for (int it = 0; it < 4; it++) {
        int task = tid + it * 128;
        int row  = task >> 3;
        int seg  = task & 7;
        cp16(dstB + SWZ(row * 128 + seg * 16),
             VT + (size_t)row * Tt + s1 + seg * 8);
    }
}

__global__ __launch_bounds__(128, 2)
void av_mma_kernel()
{
    const int t0 = ((int)gridDim.x - 1 - (int)blockIdx.x) * 128;   // heavy tiles first
    const int bh = blockIdx.y;
    const int b  = bh / Hh;
    const int hh = bh % Hh;
    const __half* S  = g_att + (size_t)bh * Tt * Tt;
    const __half* VT = g_vt + (size_t)bh * DhD * Tt;

    extern __shared__ char smem[];
    const uint32_t sbase = smem_u32(smem);
    const int tid = threadIdx.x;
    const int wid = tid >> 5, lane = tid & 31;
    const int wm = wid >> 1, wn = wid & 1;

    float acc[4][4][4];
#pragma unroll
    for (int i = 0; i < 4; i++)
#pragma unroll
        for (int j = 0; j < 4; j++)
#pragma unroll
            for (int q = 0; q < 4; q++) acc[i][j][q] = 0.f;

    const int nk = t0 / 64 + 2;
    av_load_chunk(sbase, 0, S, t0, VT, 0, tid);  CP_COMMIT();
    if (nk > 1) av_load_chunk(sbase, 1, S, t0, VT, 64, tid);
    CP_COMMIT();

    for (int c = 0; c < nk; c++) {
        CP_WAIT1();
        __syncthreads();

        if (c + 2 < nk) {
            av_load_chunk(sbase, (c + 2) % 3, S, t0, VT, (c + 2) * 64, tid);
        }
        CP_COMMIT();

        const uint32_t sa = sbase + (c % 3) * AV_STAGE;
        const uint32_t sb = sa + 16384;

#pragma unroll
        for (int kk = 0; kk < 4; kk++) {
            uint32_t afr[4][4];
#pragma unroll
            for (int i = 0; i < 4; i++) {
                int row = wm * 64 + i * 16 + (lane & 15);
                uint32_t off = row * 128 + kk * 32 + (lane >> 4) * 16;
                ldm_x4(afr[i], sa + SWZ(off));
            }
            uint32_t bfr[4][2];
#pragma unroll
            for (int p = 0; p < 2; p++) {
                int rown = wn * 32 + p * 16 + ((lane >> 4) & 1) * 8 + (lane & 7);
                uint32_t off = rown * 128 + kk * 32 + ((lane >> 3) & 1) * 16;
                uint32_t r[4];
                ldm_x4(r, sb + SWZ(off));
                bfr[2*p][0] = r[0]; bfr[2*p][1] = r[1];
                bfr[2*p+1][0] = r[2]; bfr[2*p+1][1] = r[3];
            }
#pragma unroll
            for (int i = 0; i < 4; i++)
#pragma unroll
                for (int j = 0; j < 4; j++)
                    mma16816(acc[i][j], afr[i], bfr[j]);
        }
    }

#pragma unroll
    for (int i = 0; i < 4; i++) {
        int m0 = t0 + wm * 64 + i * 16 + (lane >> 2);
        __half* r0 = g_a2L + (size_t)(b * Tt + m0) * 768 + hh * DhD;
        __half* r1 = r0 + (size_t)8 * 768;
#pragma unroll
        for (int j = 0; j < 4; j++) {
            int n = wn * 32 + j * 8 + (lane & 3) * 2;
            *(__half2*)(r0 + n) = __floats2half2_rn(acc[i][j][0], acc[i][j][1]);
            *(__half2*)(r1 + n) = __floats2half2_rn(acc[i][j][2], acc[i][j][3]);
        }
    }
}

// ---------------- 8) rowZ: combine partials, gather target logit ----------------
__global__ __launch_bounds__(256)
void rowZ_kernel(const float* __restrict__ logits, const int* __restrict__ y)
{
    int r = blockIdx.x * 256 + threadIdx.x;
    if (r >= BT) return;
    const float* pz = g_partZ + (size_t)r * NBY;
    float z = 0.f;
    for (int i = 0; i < NBY; i++) z += pz[i];
    g_rowlogp[r] = logits[(size_t)r * Vv + y[r]] - logf(z);
}

__global__ __launch_bounds__(256)
void loss_reduce_kernel(float* __restrict__ loss_out)
{
    __shared__ float sm[256];
    const int tid = threadIdx.x;
    float s = 0.f;
    for (int i = tid; i < BT; i += 256) s += g_rowlogp[i];
    sm[tid] = s;
    __syncthreads();
    for (int off = 128; off > 0; off >>= 1) {
        if (tid < off) sm[tid] += sm[tid + off];
        __syncthreads();
    }
    if (tid == 0) *loss_out = -sm[0] / (float)BT;
}

// ---------------- launch ----------------
extern "C" void kernel_launch(void* const* d_in, const int* in_sizes, int n_in,
                              void* d_out, int out_size)
{
    const int*   x    = (const int*)d_in[0];
    const int*   y    = (const int*)d_in[1];
    const float* tok  = (const float*)d_in[2];
    const float* pos  = (const float*)d_in[3];
    const float* Wq   = (const float*)d_in[4];
    const float* Wk   = (const float*)d_in[5];
    const float* Wv   = (const float*)d_in[6];
    const float* Wout = (const float*)d_in[7];
    const float* bout = (const float*)d_in[8];

    float* logits = (float*)d_out;
    float* loss   = (float*)d_out + (size_t)out_size - 1;

    __half *pa2q, *pb2q, *pa2L, *pb2L, *pqkh;
    float  *pv, *ppz;
    cudaGetSymbolAddress((void**)&pa2q, g_a2q);
    cudaGetSymbolAddress((void**)&pb2q, g_b2q);
    cudaGetSymbolAddress((void**)&pa2L, g_a2L);
    cudaGetSymbolAddress((void**)&pb2L, g_b2L);
    cudaGetSymbolAddress((void**)&pqkh, g_qkh);
    cudaGetSymbolAddress((void**)&pv,   g_v);
    cudaGetSymbolAddress((void**)&ppz,  g_partZ);

    cudaFuncSetAttribute(mma_gemm_kernel<36, 2304, 2304>,
                         cudaFuncAttributeMaxDynamicSharedMemorySize, 3 * STAGE_BYTES);
    cudaFuncSetAttribute(mma_gemm_kernel<12, 768, 768>,
                         cudaFuncAttributeMaxDynamicSharedMemorySize, 3 * STAGE_BYTES);
    cudaFuncSetAttribute(av_mma_kernel,
                         cudaFuncAttributeMaxDynamicSharedMemorySize, 3 * AV_STAGE);

    // 1) embed + split h
    embed_split_kernel<<<(BT * Ee + 255) / 256, 256>>>(x, tok, pos);
    // 2) weight conversions
    packB2q_kernel<<<(QKVN * Ee + 255) / 256, 256>>>(Wq, Wk, Wv);
    {
        dim3 grid(NPAD / 32, Ee / 32);
        dim3 blk(32, 8);
        convB_kernel<<<grid, blk>>>(Wout);
    }
    // 3) qkv (fp16 3-term, K=2304) -> q,k fp16 + v fp32
    {
        dim3 grid(BT / 128, QKVN / 128);
        mma_gemm_kernel<36, 2304, 2304><<<grid, 128, 3 * STAGE_BYTES>>>(
            pa2q, pb2q, QKVN, nullptr, nullptr, 0, 1, pqkh, pv, nullptr);
    }
    // 4) E = exp(scores) fp16 + per-tile column partial Z
    {
        dim3 grid(Tt / 128, Tt / 128, BH);
        scores_mma_kernel<<<grid, 128>>>();
    }
    // 5) invZ per column
    invZ_kernel<<<(BH * Tt + 255) / 256, 256>>>();
    // 5b) v^T fp16 with invZ folded in
    {
        dim3 grid(Tt / 32, Ee / 32, Bb);
        dim3 blk(32, 8);
        vt_kernel<<<grid, blk>>>();
    }
    // 6) o = E @ (invZ*v) on tensor pipe (pure GEMM)
    {
        dim3 grid(Tt / 128, BH);
        av_mma_kernel<<<grid, 128, 3 * AV_STAGE>>>();
    }
    // 7) logits (fp16 1-term, K=768) + fused partial sumexp
    {
        dim3 grid(BT / 128, NBY);
        mma_gemm_kernel<12, 768, 768><<<grid, 128, 3 * STAGE_BYTES>>>(
            pa2L, pb2L, Vv, bout, logits, Vv, 0, nullptr, nullptr, ppz);
    }
    // 8) loss
    rowZ_kernel<<<(BT + 255) / 256, 256>>>(logits, y);
    loss_reduce_kernel<<<1, 256>>>(loss);
}